// round 8
// baseline (speedup 1.0000x reference)
#include <cuda_runtime.h>
#include <cuda_fp16.h>
#include <cstdint>

#define DF 128
#define NMAX 100000
#define EMAX 1600000
#define GMAX 1024

// persistent scratch (no allocations allowed)
__device__ float  g_bufA[(size_t)NMAX * DF];
__device__ float  g_bufC[(size_t)NMAX * DF];
__device__ __half g_h16[(size_t)NMAX * DF];
__device__ float  g_pool[(size_t)GMAX * DF];
__device__ int    g_deg[NMAX];
__device__ int    g_rowptr[NMAX + 1];
__device__ int    g_cursor[NMAX];
__device__ int    g_csrc[EMAX];
__device__ int    g_bsum[1024];

__device__ __forceinline__ float to_tf32(float f) {
    float o;
    asm("cvt.rna.tf32.f32 %0, %1;" : "=f"(o) : "f"(f));
    return o;
}

// ---------------------------------------------------------------------------
// CSR build: degree histogram -> exclusive scan -> scatter
__global__ void deg_kernel(const int* __restrict__ dst, int* __restrict__ deg, int E) {
    int i = blockIdx.x * blockDim.x + threadIdx.x;
    if (i < E) atomicAdd(&deg[__ldg(dst + i)], 1);
}

__global__ void scan1_kernel(const int* __restrict__ deg, int* __restrict__ rowptr,
                             int* __restrict__ bsum, int N) {
    __shared__ int sh[1024];
    int tid = threadIdx.x;
    int i = blockIdx.x * 1024 + tid;
    int v = (i < N) ? deg[i] : 0;
    sh[tid] = v;
    __syncthreads();
    #pragma unroll
    for (int off = 1; off < 1024; off <<= 1) {
        int t = (tid >= off) ? sh[tid - off] : 0;
        __syncthreads();
        sh[tid] += t;
        __syncthreads();
    }
    if (i < N) rowptr[i] = sh[tid] - v;
    if (tid == 1023) bsum[blockIdx.x] = sh[1023];
}

__global__ void scan2_kernel(int* __restrict__ bsum, int nb) {
    if (threadIdx.x == 0 && blockIdx.x == 0) {
        int acc = 0;
        for (int i = 0; i < nb; ++i) {
            int v = bsum[i];
            bsum[i] = acc;
            acc += v;
        }
    }
}

__global__ void scan3_kernel(int* __restrict__ rowptr, const int* __restrict__ bsum,
                             int N, int E) {
    int i = blockIdx.x * 1024 + threadIdx.x;
    if (i < N) rowptr[i] += bsum[blockIdx.x];
    if (i == 0) rowptr[N] = E;
}

__global__ void scatter_kernel(const int* __restrict__ src, const int* __restrict__ dst,
                               int* __restrict__ cursor, int* __restrict__ csrc, int E) {
    int i = blockIdx.x * blockDim.x + threadIdx.x;
    if (i < E) {
        int pos = atomicAdd(&cursor[__ldg(dst + i)], 1);
        csrc[pos] = __ldg(src + i);
    }
}

// ---------------------------------------------------------------------------
// fp32 -> fp16 convert (initial h only)
__global__ void cvt16_kernel(const float* __restrict__ src, __half* __restrict__ dst, int n4) {
    int i = blockIdx.x * blockDim.x + threadIdx.x;
    if (i < n4) {
        float4 v = *(const float4*)(src + i * 4);
        __half2 p2[2];
        p2[0] = __floats2half2_rn(v.x, v.y);
        p2[1] = __floats2half2_rn(v.z, v.w);
        *(float2*)(dst + i * 4) = *(float2*)p2;
    }
}

// ---------------------------------------------------------------------------
// Pull aggregation from fp16 h copy: one warp per dst node, fp32 accumulation.
// Each lane loads 4 cols (8 bytes = 2 half2) per neighbor.
__global__ void agg_kernel(const __half* __restrict__ h16, const int* __restrict__ rowptr,
                           const int* __restrict__ csrc, float* __restrict__ agg, int N) {
    int v    = (blockIdx.x * blockDim.x + threadIdx.x) >> 5;
    int lane = threadIdx.x & 31;
    if (v >= N) return;
    int beg = __ldg(rowptr + v), end = __ldg(rowptr + v + 1);
    float4 acc = make_float4(0.f, 0.f, 0.f, 0.f);
    int i = beg;
    for (; i + 4 <= end; i += 4) {
        int u0 = __ldg(csrc + i), u1 = __ldg(csrc + i + 1);
        int u2 = __ldg(csrc + i + 2), u3 = __ldg(csrc + i + 3);
        const __half2* q0 = (const __half2*)(h16 + (size_t)u0 * DF + lane * 4);
        const __half2* q1 = (const __half2*)(h16 + (size_t)u1 * DF + lane * 4);
        const __half2* q2 = (const __half2*)(h16 + (size_t)u2 * DF + lane * 4);
        const __half2* q3 = (const __half2*)(h16 + (size_t)u3 * DF + lane * 4);
        __half2 a0 = q0[0], a1 = q0[1];
        __half2 b0 = q1[0], b1 = q1[1];
        __half2 c0 = q2[0], c1 = q2[1];
        __half2 d0 = q3[0], d1 = q3[1];
        float2 fa0 = __half22float2(a0), fa1 = __half22float2(a1);
        float2 fb0 = __half22float2(b0), fb1 = __half22float2(b1);
        float2 fc0 = __half22float2(c0), fc1 = __half22float2(c1);
        float2 fd0 = __half22float2(d0), fd1 = __half22float2(d1);
        acc.x += fa0.x + fb0.x + fc0.x + fd0.x;
        acc.y += fa0.y + fb0.y + fc0.y + fd0.y;
        acc.z += fa1.x + fb1.x + fc1.x + fd1.x;
        acc.w += fa1.y + fb1.y + fc1.y + fd1.y;
    }
    for (; i < end; ++i) {
        int u = __ldg(csrc + i);
        const __half2* q = (const __half2*)(h16 + (size_t)u * DF + lane * 4);
        float2 f0 = __half22float2(q[0]);
        float2 f1 = __half22float2(q[1]);
        acc.x += f0.x; acc.y += f0.y; acc.z += f1.x; acc.w += f1.y;
    }
    *(float4*)(agg + (size_t)v * DF + lane * 4) = acc;
}

// ---------------------------------------------------------------------------
// Fully fused GIN layer MLP: persistent kernel, both W1 and W2 in smem.
// 512 threads (16 warps); warp tile 16x64. Writes fp32 h and fp16 copy.
__global__ void __launch_bounds__(512, 1)
layer_fused(const float* __restrict__ x, const float* __restrict__ hres,
            const float* __restrict__ epsArr, int layer,
            const float* __restrict__ W1, const float* __restrict__ b1,
            const float* __restrict__ g1, const float* __restrict__ be1,
            const float* __restrict__ W2, const float* __restrict__ b2,
            const float* __restrict__ ng, const float* __restrict__ nb,
            float* __restrict__ out, __half* __restrict__ out16,
            int nrows, int ntiles) {
    extern __shared__ float smem[];
    float* Ws1 = smem;                   // 16384 floats
    float* Ws2 = smem + 16384;           // 16384 floats
    float* Xs  = smem + 32768;           // [128 rows][136] = 17408 floats
    float* prm = smem + 32768 + 17408;   // 6 x 128
    float* bs1 = prm, *gs1 = prm + 128, *es1 = prm + 256;
    float* bs2 = prm + 384, *gs2 = prm + 512, *es2 = prm + 640;

    int tid  = threadIdx.x;
    int lane = tid & 31, warp = tid >> 5;

    #pragma unroll
    for (int idx = tid; idx < 4096; idx += 512) {
        int n4  = idx & 31;
        int skk = idx >> 5;
        int s   = skk >> 3, kk = skk & 7;
        int c   = kk >> 1;
        int kphys = (kk & 1) ? (c + 4) : c;
        size_t go = (size_t)(8 * s + kphys) * DF + n4 * 4;
        float4 wa = *(const float4*)(W1 + go);
        float4 wb = *(const float4*)(W2 + go);
        float* pa = &Ws1[((s * 128 + n4 * 4) << 3) + kk];
        float* pb = &Ws2[((s * 128 + n4 * 4) << 3) + kk];
        pa[0] = to_tf32(wa.x); pa[8] = to_tf32(wa.y); pa[16] = to_tf32(wa.z); pa[24] = to_tf32(wa.w);
        pb[0] = to_tf32(wb.x); pb[8] = to_tf32(wb.y); pb[16] = to_tf32(wb.z); pb[24] = to_tf32(wb.w);
    }
    if (tid < DF) {
        bs1[tid] = b1[tid]; gs1[tid] = g1[tid]; es1[tid] = be1[tid];
        bs2[tid] = b2[tid]; gs2[tid] = ng[tid]; es2[tid] = nb[tid];
    }

    float escale = 1.0f + epsArr[layer];

    int wr = (warp & 7) * 16;
    int wc = (warp >> 3) * 64;
    int fr = lane >> 2;
    int c2 = (lane & 3) * 2;

    __syncthreads();

    for (int tile = blockIdx.x; tile < ntiles; tile += gridDim.x) {
        int rowBlk = tile * 128;

        // ---- stage X + residual (tf32, interleaved) ----
        #pragma unroll
        for (int idx = tid; idx < 128 * 32; idx += 512) {
            int r = idx >> 5, c4 = idx & 31;
            int row = rowBlk + r;
            float4 v = make_float4(0.f, 0.f, 0.f, 0.f);
            if (row < nrows) {
                v = *(const float4*)(x + (size_t)row * DF + c4 * 4);
                float4 hv = *(const float4*)(hres + (size_t)row * DF + c4 * 4);
                v.x = fmaf(escale, hv.x, v.x);
                v.y = fmaf(escale, hv.y, v.y);
                v.z = fmaf(escale, hv.z, v.z);
                v.w = fmaf(escale, hv.w, v.w);
            }
            float* p = &Xs[r * 136 + (c4 >> 1) * 8 + (c4 & 1)];
            p[0] = to_tf32(v.x);
            p[2] = to_tf32(v.y);
            p[4] = to_tf32(v.z);
            p[6] = to_tf32(v.w);
        }
        __syncthreads();

        float acc[8][4];

        // ================= pass 1: X @ W1 =================
        #pragma unroll
        for (int j = 0; j < 8; ++j) {
            acc[j][0] = 0.f; acc[j][1] = 0.f; acc[j][2] = 0.f; acc[j][3] = 0.f;
        }
        #pragma unroll
        for (int s = 0; s < 16; ++s) {
            const float* xp = &Xs[(wr + fr) * 136 + s * 8 + c2];
            float2 alo = *(const float2*)xp;
            float2 ahi = *(const float2*)(xp + 8 * 136);
            uint32_t a0 = __float_as_uint(alo.x), a2 = __float_as_uint(alo.y);
            uint32_t a1 = __float_as_uint(ahi.x), a3 = __float_as_uint(ahi.y);
            const float* wp = &Ws1[((s * 128) + wc + fr) * 8 + c2];
            #pragma unroll
            for (int j = 0; j < 8; ++j) {
                float2 bvj = *(const float2*)(wp + j * 64);
                uint32_t b0 = __float_as_uint(bvj.x), bq = __float_as_uint(bvj.y);
                asm volatile(
                    "mma.sync.aligned.m16n8k8.row.col.f32.tf32.tf32.f32 "
                    "{%0,%1,%2,%3}, {%4,%5,%6,%7}, {%8,%9}, {%0,%1,%2,%3};"
                    : "+f"(acc[j][0]), "+f"(acc[j][1]), "+f"(acc[j][2]), "+f"(acc[j][3])
                    : "r"(a0), "r"(a1), "r"(a2), "r"(a3), "r"(b0), "r"(bq));
            }
        }
        __syncthreads();
        #pragma unroll
        for (int j = 0; j < 8; ++j) {
            int n = wc + j * 8 + c2;
            *(float2*)&Xs[(wr + fr) * 136 + n]     = make_float2(acc[j][0], acc[j][1]);
            *(float2*)&Xs[(wr + fr + 8) * 136 + n] = make_float2(acc[j][2], acc[j][3]);
        }
        __syncthreads();

        // ---- LN1 + ReLU, in-place re-permute to tf32 A-layout ----
        {
            float4 b4 = ((const float4*)bs1)[lane];
            float4 g4 = ((const float4*)gs1)[lane];
            float4 e4 = ((const float4*)es1)[lane];
            #pragma unroll
            for (int rr = 0; rr < 8; ++rr) {
                int lrow = warp * 8 + rr;
                float* R = &Xs[lrow * 136];
                float4 aa = *(const float4*)&R[lane * 4];
                float a0 = aa.x + b4.x, a1 = aa.y + b4.y, a2 = aa.z + b4.z, a3 = aa.w + b4.w;
                float s = a0 + a1 + a2 + a3;
                float q = a0 * a0 + a1 * a1 + a2 * a2 + a3 * a3;
                #pragma unroll
                for (int off = 16; off > 0; off >>= 1) {
                    s += __shfl_xor_sync(0xFFFFFFFFu, s, off);
                    q += __shfl_xor_sync(0xFFFFFFFFu, q, off);
                }
                float mu   = s * (1.0f / 128.0f);
                float var  = q * (1.0f / 128.0f) - mu * mu;
                float rstd = rsqrtf(var + 1e-5f);
                float o0 = fmaxf(0.f, (a0 - mu) * rstd * g4.x + e4.x);
                float o1 = fmaxf(0.f, (a1 - mu) * rstd * g4.y + e4.y);
                float o2 = fmaxf(0.f, (a2 - mu) * rstd * g4.z + e4.z);
                float o3 = fmaxf(0.f, (a3 - mu) * rstd * g4.w + e4.w);
                int kc = lane * 4;
                int grp = (kc >> 3) * 8;
                int c0 = kc & 7;
                int p0 = grp + ((c0 < 4) ? 2 * c0 : 2 * (c0 - 4) + 1);
                R[p0]     = to_tf32(o0);
                R[p0 + 2] = to_tf32(o1);
                R[p0 + 4] = to_tf32(o2);
                R[p0 + 6] = to_tf32(o3);
            }
        }
        __syncthreads();

        // ================= pass 2: Y @ W2 =================
        #pragma unroll
        for (int j = 0; j < 8; ++j) {
            acc[j][0] = 0.f; acc[j][1] = 0.f; acc[j][2] = 0.f; acc[j][3] = 0.f;
        }
        #pragma unroll
        for (int s = 0; s < 16; ++s) {
            const float* xp = &Xs[(wr + fr) * 136 + s * 8 + c2];
            float2 alo = *(const float2*)xp;
            float2 ahi = *(const float2*)(xp + 8 * 136);
            uint32_t a0 = __float_as_uint(alo.x), a2 = __float_as_uint(alo.y);
            uint32_t a1 = __float_as_uint(ahi.x), a3 = __float_as_uint(ahi.y);
            const float* wp = &Ws2[((s * 128) + wc + fr) * 8 + c2];
            #pragma unroll
            for (int j = 0; j < 8; ++j) {
                float2 bvj = *(const float2*)(wp + j * 64);
                uint32_t b0 = __float_as_uint(bvj.x), bq = __float_as_uint(bvj.y);
                asm volatile(
                    "mma.sync.aligned.m16n8k8.row.col.f32.tf32.tf32.f32 "
                    "{%0,%1,%2,%3}, {%4,%5,%6,%7}, {%8,%9}, {%0,%1,%2,%3};"
                    : "+f"(acc[j][0]), "+f"(acc[j][1]), "+f"(acc[j][2]), "+f"(acc[j][3])
                    : "r"(a0), "r"(a1), "r"(a2), "r"(a3), "r"(b0), "r"(bq));
            }
        }
        __syncthreads();
        #pragma unroll
        for (int j = 0; j < 8; ++j) {
            int n = wc + j * 8 + c2;
            *(float2*)&Xs[(wr + fr) * 136 + n]     = make_float2(acc[j][0], acc[j][1]);
            *(float2*)&Xs[(wr + fr + 8) * 136 + n] = make_float2(acc[j][2], acc[j][3]);
        }
        __syncthreads();

        // ---- LN2 + ReLU -> gmem (fp32 + fp16 copy) ----
        {
            float4 b4 = ((const float4*)bs2)[lane];
            float4 g4 = ((const float4*)gs2)[lane];
            float4 e4 = ((const float4*)es2)[lane];
            #pragma unroll
            for (int rr = 0; rr < 8; ++rr) {
                int lrow = warp * 8 + rr;
                int grow = rowBlk + lrow;
                float4 aa = *(const float4*)&Xs[lrow * 136 + lane * 4];
                float a0 = aa.x + b4.x, a1 = aa.y + b4.y, a2 = aa.z + b4.z, a3 = aa.w + b4.w;
                float s = a0 + a1 + a2 + a3;
                float q = a0 * a0 + a1 * a1 + a2 * a2 + a3 * a3;
                #pragma unroll
                for (int off = 16; off > 0; off >>= 1) {
                    s += __shfl_xor_sync(0xFFFFFFFFu, s, off);
                    q += __shfl_xor_sync(0xFFFFFFFFu, q, off);
                }
                float mu   = s * (1.0f / 128.0f);
                float var  = q * (1.0f / 128.0f) - mu * mu;
                float rstd = rsqrtf(var + 1e-5f);
                float4 o;
                o.x = fmaxf(0.f, (a0 - mu) * rstd * g4.x + e4.x);
                o.y = fmaxf(0.f, (a1 - mu) * rstd * g4.y + e4.y);
                o.z = fmaxf(0.f, (a2 - mu) * rstd * g4.z + e4.z);
                o.w = fmaxf(0.f, (a3 - mu) * rstd * g4.w + e4.w);
                if (grow < nrows) {
                    *(float4*)(out + (size_t)grow * DF + lane * 4) = o;
                    __half2 p2[2];
                    p2[0] = __floats2half2_rn(o.x, o.y);
                    p2[1] = __floats2half2_rn(o.z, o.w);
                    *(float2*)(out16 + (size_t)grow * DF + lane * 4) = *(float2*)p2;
                }
            }
        }
        __syncthreads();
    }
}

// ---------------------------------------------------------------------------
__global__ void pool_kernel(const float* __restrict__ h, const int* __restrict__ gid,
                            float* __restrict__ pool, int N) {
    int c  = threadIdx.x;
    int n0 = blockIdx.x * 128;
    if (n0 >= N) return;
    int curg = __ldg(gid + n0);
    float acc = 0.f;
    #pragma unroll 4
    for (int i = 0; i < 128; ++i) {
        int n = n0 + i;
        if (n >= N) break;
        int g = __ldg(gid + n);
        if (g != curg) {
            atomicAdd(&pool[(size_t)curg * DF + c], acc);
            acc = 0.f;
            curg = g;
        }
        acc += __ldg(h + (size_t)n * DF + c);
    }
    atomicAdd(&pool[(size_t)curg * DF + c], acc);
}

// ---------------------------------------------------------------------------
__global__ void head_kernel(const float* __restrict__ pool, const float* __restrict__ desc,
                            const float* __restrict__ fc1W, const float* __restrict__ fc1b,
                            const float* __restrict__ n1g, const float* __restrict__ n1b,
                            const float* __restrict__ fc2W, const float* __restrict__ fc2b,
                            float* __restrict__ out, int X, int C) {
    int g = blockIdx.x;
    int t = threadIdx.x;
    int warp = t >> 5, lane = t & 31;

    __shared__ float xin[DF + 64];
    __shared__ float ss[4], qq[4];

    xin[t] = pool[(size_t)g * DF + t];
    if (t < X) xin[DF + t] = desc[(size_t)g * X + t];
    __syncthreads();

    int K = DF + X;
    float acc = fc1b[t];
    for (int k = 0; k < K; ++k)
        acc = fmaf(xin[k], __ldg(fc1W + (size_t)k * DF + t), acc);

    float s = acc, q = acc * acc;
    #pragma unroll
    for (int off = 16; off > 0; off >>= 1) {
        s += __shfl_xor_sync(0xFFFFFFFFu, s, off);
        q += __shfl_xor_sync(0xFFFFFFFFu, q, off);
    }
    if (lane == 0) { ss[warp] = s; qq[warp] = q; }
    __syncthreads();
    s = ss[0] + ss[1] + ss[2] + ss[3];
    q = qq[0] + qq[1] + qq[2] + qq[3];
    float mu   = s * (1.0f / 128.0f);
    float var  = q * (1.0f / 128.0f) - mu * mu;
    float rstd = rsqrtf(var + 1e-5f);
    float y = fmaxf(0.f, (acc - mu) * rstd * n1g[t] + n1b[t]);

    for (int c = 0; c < C; ++c) {
        float p = y * __ldg(fc2W + (size_t)t * C + c);
        #pragma unroll
        for (int off = 16; off > 0; off >>= 1)
            p += __shfl_xor_sync(0xFFFFFFFFu, p, off);
        __syncthreads();
        if (lane == 0) ss[warp] = p;
        __syncthreads();
        if (t == 0) out[(size_t)g * C + c] = ss[0] + ss[1] + ss[2] + ss[3] + fc2b[c];
    }
}

// ---------------------------------------------------------------------------
extern "C" void kernel_launch(void* const* d_in, const int* in_sizes, int n_in,
                              void* d_out, int out_size) {
    const float* h    = (const float*)d_in[0];
    const float* desc = (const float*)d_in[1];
    const int*   src  = (const int*)d_in[2];
    const int*   dst  = (const int*)d_in[3];
    const int*   gid  = (const int*)d_in[4];
    const float* W1   = (const float*)d_in[5];
    const float* b1   = (const float*)d_in[6];
    const float* g1   = (const float*)d_in[7];
    const float* be1  = (const float*)d_in[8];
    const float* W2   = (const float*)d_in[9];
    const float* b2   = (const float*)d_in[10];
    const float* eps  = (const float*)d_in[11];
    const float* ng   = (const float*)d_in[12];
    const float* nb   = (const float*)d_in[13];
    const float* fc1W = (const float*)d_in[14];
    const float* fc1b = (const float*)d_in[15];
    const float* n1g  = (const float*)d_in[16];
    const float* n1b  = (const float*)d_in[17];
    const float* fc2W = (const float*)d_in[18];
    const float* fc2b = (const float*)d_in[19];
    float* out = (float*)d_out;

    int N = in_sizes[0] / DF;
    int E = in_sizes[2];
    int L = in_sizes[11];
    int X = in_sizes[14] / DF - DF;
    if (X <= 0) X = 16;
    int G = in_sizes[1] / X;
    int C = in_sizes[18] / DF;
    if (C <= 0) C = 1;
    if (N > NMAX) N = NMAX;
    if (G > GMAX) G = GMAX;
    if (E > EMAX) E = EMAX;

    float *bufA, *bufC, *pool;
    __half* h16;
    int *degp, *rowptr, *cursor, *csrc, *bsum;
    cudaGetSymbolAddress((void**)&bufA, g_bufA);
    cudaGetSymbolAddress((void**)&bufC, g_bufC);
    cudaGetSymbolAddress((void**)&h16,  g_h16);
    cudaGetSymbolAddress((void**)&pool, g_pool);
    cudaGetSymbolAddress((void**)&degp, g_deg);
    cudaGetSymbolAddress((void**)&rowptr, g_rowptr);
    cudaGetSymbolAddress((void**)&cursor, g_cursor);
    cudaGetSymbolAddress((void**)&csrc, g_csrc);
    cudaGetSymbolAddress((void**)&bsum, g_bsum);

    const int SMEM_BYTES = (2 * 16384 + 17408 + 6 * DF) * sizeof(float); // 203,776
    cudaFuncSetAttribute(layer_fused,
                         cudaFuncAttributeMaxDynamicSharedMemorySize, SMEM_BYTES);

    // --- CSR build + fp16 convert of input h (independent, once per launch) ---
    int nb_scan = (N + 1023) / 1024;
    cudaMemsetAsync(degp, 0, (size_t)N * sizeof(int));
    deg_kernel<<<(E + 255) / 256, 256>>>(dst, degp, E);
    scan1_kernel<<<nb_scan, 1024>>>(degp, rowptr, bsum, N);
    scan2_kernel<<<1, 32>>>(bsum, nb_scan);
    scan3_kernel<<<nb_scan, 1024>>>(rowptr, bsum, N, E);
    cudaMemcpyAsync(cursor, rowptr, (size_t)N * sizeof(int), cudaMemcpyDeviceToDevice);
    scatter_kernel<<<(E + 255) / 256, 256>>>(src, dst, cursor, csrc, E);
    int nd4 = N * (DF / 4);
    cvt16_kernel<<<(nd4 + 255) / 256, 256>>>(h, h16, nd4);

    int ntiles = (N + 127) / 128;
    int fgrid = ntiles < 148 ? ntiles : 148;
    int agg_grid = (N * 32 + 255) / 256;

    const float* hcur = h;
    for (int l = 0; l < L; ++l) {
        agg_kernel<<<agg_grid, 256>>>(h16, rowptr, csrc, bufA, N);
        layer_fused<<<fgrid, 512, SMEM_BYTES>>>(
            bufA, hcur, eps, l,
            W1 + (size_t)l * DF * DF, b1 + (size_t)l * DF,
            g1 + (size_t)l * DF, be1 + (size_t)l * DF,
            W2 + (size_t)l * DF * DF, b2 + (size_t)l * DF,
            ng + (size_t)l * DF, nb + (size_t)l * DF,
            bufC, h16, N, ntiles);
        hcur = bufC;
    }

    cudaMemsetAsync(pool, 0, (size_t)G * DF * sizeof(float));
    pool_kernel<<<(N + 127) / 128, 128>>>(hcur, gid, pool, N);
    head_kernel<<<G, 128>>>(pool, desc, fc1W, fc1b, n1g, n1b, fc2W, fc2b, out, X, C);
}

// round 9
// speedup vs baseline: 1.0946x; 1.0946x over previous
#include <cuda_runtime.h>
#include <cuda_fp16.h>
#include <cstdint>

#define DF 128
#define NMAX 100000
#define EMAX 1600000
#define GMAX 1024

// persistent scratch (no allocations allowed)
__device__ float  g_bufA[(size_t)NMAX * DF];
__device__ float  g_bufC[(size_t)NMAX * DF];
__device__ __half g_h16[(size_t)NMAX * DF];
__device__ float  g_pool[(size_t)GMAX * DF];
__device__ int    g_deg[NMAX];
__device__ int    g_rowptr[NMAX + 1];
__device__ int    g_cursor[NMAX];
__device__ int    g_csrc[EMAX];
__device__ int    g_bsum[1024];

// ---------------------------------------------------------------------------
// CSR build: degree histogram -> exclusive scan -> scatter
__global__ void deg_kernel(const int* __restrict__ dst, int* __restrict__ deg, int E) {
    int i = blockIdx.x * blockDim.x + threadIdx.x;
    if (i < E) atomicAdd(&deg[__ldg(dst + i)], 1);
}

__global__ void scan1_kernel(const int* __restrict__ deg, int* __restrict__ rowptr,
                             int* __restrict__ bsum, int N) {
    __shared__ int sh[1024];
    int tid = threadIdx.x;
    int i = blockIdx.x * 1024 + tid;
    int v = (i < N) ? deg[i] : 0;
    sh[tid] = v;
    __syncthreads();
    #pragma unroll
    for (int off = 1; off < 1024; off <<= 1) {
        int t = (tid >= off) ? sh[tid - off] : 0;
        __syncthreads();
        sh[tid] += t;
        __syncthreads();
    }
    if (i < N) rowptr[i] = sh[tid] - v;
    if (tid == 1023) bsum[blockIdx.x] = sh[1023];
}

__global__ void scan2_kernel(int* __restrict__ bsum, int nb) {
    if (threadIdx.x == 0 && blockIdx.x == 0) {
        int acc = 0;
        for (int i = 0; i < nb; ++i) {
            int v = bsum[i];
            bsum[i] = acc;
            acc += v;
        }
    }
}

__global__ void scan3_kernel(int* __restrict__ rowptr, const int* __restrict__ bsum,
                             int N, int E) {
    int i = blockIdx.x * 1024 + threadIdx.x;
    if (i < N) rowptr[i] += bsum[blockIdx.x];
    if (i == 0) rowptr[N] = E;
}

__global__ void scatter_kernel(const int* __restrict__ src, const int* __restrict__ dst,
                               int* __restrict__ cursor, int* __restrict__ csrc, int E) {
    int i = blockIdx.x * blockDim.x + threadIdx.x;
    if (i < E) {
        int pos = atomicAdd(&cursor[__ldg(dst + i)], 1);
        csrc[pos] = __ldg(src + i);
    }
}

// ---------------------------------------------------------------------------
// fp32 -> fp16 convert (initial h only)
__global__ void cvt16_kernel(const float* __restrict__ src, __half* __restrict__ dst, int n4) {
    int i = blockIdx.x * blockDim.x + threadIdx.x;
    if (i < n4) {
        float4 v = *(const float4*)(src + i * 4);
        __half2 p2[2];
        p2[0] = __floats2half2_rn(v.x, v.y);
        p2[1] = __floats2half2_rn(v.z, v.w);
        *(float2*)(dst + i * 4) = *(float2*)p2;
    }
}

// ---------------------------------------------------------------------------
// Pull aggregation from fp16 h copy: one warp per dst node, fp32 accumulation.
__global__ void agg_kernel(const __half* __restrict__ h16, const int* __restrict__ rowptr,
                           const int* __restrict__ csrc, float* __restrict__ agg, int N) {
    int v    = (blockIdx.x * blockDim.x + threadIdx.x) >> 5;
    int lane = threadIdx.x & 31;
    if (v >= N) return;
    int beg = __ldg(rowptr + v), end = __ldg(rowptr + v + 1);
    float4 acc = make_float4(0.f, 0.f, 0.f, 0.f);
    int i = beg;
    for (; i + 4 <= end; i += 4) {
        int u0 = __ldg(csrc + i), u1 = __ldg(csrc + i + 1);
        int u2 = __ldg(csrc + i + 2), u3 = __ldg(csrc + i + 3);
        const __half2* q0 = (const __half2*)(h16 + (size_t)u0 * DF + lane * 4);
        const __half2* q1 = (const __half2*)(h16 + (size_t)u1 * DF + lane * 4);
        const __half2* q2 = (const __half2*)(h16 + (size_t)u2 * DF + lane * 4);
        const __half2* q3 = (const __half2*)(h16 + (size_t)u3 * DF + lane * 4);
        __half2 a0 = q0[0], a1 = q0[1];
        __half2 b0 = q1[0], b1 = q1[1];
        __half2 c0 = q2[0], c1 = q2[1];
        __half2 d0 = q3[0], d1 = q3[1];
        float2 fa0 = __half22float2(a0), fa1 = __half22float2(a1);
        float2 fb0 = __half22float2(b0), fb1 = __half22float2(b1);
        float2 fc0 = __half22float2(c0), fc1 = __half22float2(c1);
        float2 fd0 = __half22float2(d0), fd1 = __half22float2(d1);
        acc.x += fa0.x + fb0.x + fc0.x + fd0.x;
        acc.y += fa0.y + fb0.y + fc0.y + fd0.y;
        acc.z += fa1.x + fb1.x + fc1.x + fd1.x;
        acc.w += fa1.y + fb1.y + fc1.y + fd1.y;
    }
    for (; i < end; ++i) {
        int u = __ldg(csrc + i);
        const __half2* q = (const __half2*)(h16 + (size_t)u * DF + lane * 4);
        float2 f0 = __half22float2(q[0]);
        float2 f1 = __half22float2(q[1]);
        acc.x += f0.x; acc.y += f0.y; acc.z += f1.x; acc.w += f1.y;
    }
    *(float4*)(agg + (size_t)v * DF + lane * 4) = acc;
}

// ---------------------------------------------------------------------------
// Fully fused GIN layer MLP with fp16 HMMA m16n8k16, fp32 accum.
// 512 threads (16 warps), warp tile 16x64, occupancy 2 (smem ~103KB).
// k-interleave within 16-k groups: order [0,1,8,9, 2,3,10,11, 4,5,12,13, 6,7,14,15]
//  -> each A/B fragment is one LDS.64 (4 halfs: k,k+1,k+8,k+9).
// Xs row stride 144 halfs (288B) for conflict-free A loads.
#define XS_STRIDE 144

__global__ void __launch_bounds__(512, 2)
layer_fused(const float* __restrict__ x, const float* __restrict__ hres,
            const float* __restrict__ epsArr, int layer,
            const float* __restrict__ W1, const float* __restrict__ b1,
            const float* __restrict__ g1, const float* __restrict__ be1,
            const float* __restrict__ W2, const float* __restrict__ b2,
            const float* __restrict__ ng, const float* __restrict__ nb,
            float* __restrict__ out, __half* __restrict__ out16,
            int nrows, int ntiles) {
    extern __shared__ __align__(16) char smraw[];
    __half* Ws1 = (__half*)smraw;                       // 128*128 halfs = 32KB
    __half* Ws2 = Ws1 + 128 * 128;                      // 32KB
    __half* Xs  = Ws2 + 128 * 128;                      // 128*144 halfs = 36,864B
    float*  prm = (float*)(Xs + 128 * XS_STRIDE);       // 6*128 floats
    float* bs1 = prm, *gs1 = prm + 128, *es1 = prm + 256;
    float* bs2 = prm + 384, *gs2 = prm + 512, *es2 = prm + 640;

    int tid  = threadIdx.x;
    int lane = tid & 31, warp = tid >> 5;

    // Stage W1/W2 as half, interleaved: Ws[(s*128+n)*16 + pos(k&15)]
    for (int idx = tid; idx < 4096; idx += 512) {
        int k  = idx >> 5;
        int n4 = idx & 31;
        int s  = k >> 4, kq = k & 15;
        int pos = (kq & 1) | (((kq >> 3) & 1) << 1) | (((kq >> 1) & 3) << 2);
        size_t go = (size_t)k * DF + n4 * 4;
        float4 wa = *(const float4*)(W1 + go);
        float4 wb = *(const float4*)(W2 + go);
        int base = ((s * 128) + n4 * 4) * 16 + pos;
        Ws1[base]      = __float2half(wa.x);
        Ws1[base + 16] = __float2half(wa.y);
        Ws1[base + 32] = __float2half(wa.z);
        Ws1[base + 48] = __float2half(wa.w);
        Ws2[base]      = __float2half(wb.x);
        Ws2[base + 16] = __float2half(wb.y);
        Ws2[base + 32] = __float2half(wb.z);
        Ws2[base + 48] = __float2half(wb.w);
    }
    if (tid < DF) {
        bs1[tid] = b1[tid]; gs1[tid] = g1[tid]; es1[tid] = be1[tid];
        bs2[tid] = b2[tid]; gs2[tid] = ng[tid]; es2[tid] = nb[tid];
    }

    float escale = 1.0f + epsArr[layer];

    int wr = (warp & 7) * 16;      // warp row base
    int wc = (warp >> 3) * 64;     // warp col base
    int fr = lane >> 2;
    int qd = lane & 3;

    __syncthreads();

    for (int tile = blockIdx.x; tile < ntiles; tile += gridDim.x) {
        int rowBlk = tile * 128;

        // ---- stage X + residual -> half, interleaved A-layout ----
        for (int idx = tid; idx < 128 * 32; idx += 512) {
            int r = idx >> 5, c4 = idx & 31;
            int row = rowBlk + r;
            float4 v = make_float4(0.f, 0.f, 0.f, 0.f);
            if (row < nrows) {
                v = *(const float4*)(x + (size_t)row * DF + c4 * 4);
                float4 hv = *(const float4*)(hres + (size_t)row * DF + c4 * 4);
                v.x = fmaf(escale, hv.x, v.x);
                v.y = fmaf(escale, hv.y, v.y);
                v.z = fmaf(escale, hv.z, v.z);
                v.w = fmaf(escale, hv.w, v.w);
            }
            int a = (c4 & 1) * 8 + (c4 & 2);
            __half* p = Xs + r * XS_STRIDE + (c4 >> 2) * 16 + a;
            *(__half2*)p       = __floats2half2_rn(v.x, v.y);
            *(__half2*)(p + 4) = __floats2half2_rn(v.z, v.w);
        }
        __syncthreads();

        float acc[8][4];

        // ================= pass 1: X @ W1 =================
        #pragma unroll
        for (int j = 0; j < 8; ++j) {
            acc[j][0] = 0.f; acc[j][1] = 0.f; acc[j][2] = 0.f; acc[j][3] = 0.f;
        }
        #pragma unroll
        for (int s = 0; s < 8; ++s) {
            uint2 av0 = *(const uint2*)(Xs + (wr + fr)     * XS_STRIDE + s * 16 + qd * 4);
            uint2 av1 = *(const uint2*)(Xs + (wr + fr + 8) * XS_STRIDE + s * 16 + qd * 4);
            #pragma unroll
            for (int j = 0; j < 8; ++j) {
                uint2 bv = *(const uint2*)(Ws1 + ((s * 128) + wc + j * 8 + fr) * 16 + qd * 4);
                asm volatile(
                    "mma.sync.aligned.m16n8k16.row.col.f32.f16.f16.f32 "
                    "{%0,%1,%2,%3}, {%4,%5,%6,%7}, {%8,%9}, {%0,%1,%2,%3};"
                    : "+f"(acc[j][0]), "+f"(acc[j][1]), "+f"(acc[j][2]), "+f"(acc[j][3])
                    : "r"(av0.x), "r"(av1.x), "r"(av0.y), "r"(av1.y),
                      "r"(bv.x), "r"(bv.y));
            }
        }
        __syncthreads();
        // store C natural (half): cols n at Xs[row*stride + n]
        #pragma unroll
        for (int j = 0; j < 8; ++j) {
            int n = wc + j * 8 + qd * 2;
            *(__half2*)(Xs + (wr + fr)     * XS_STRIDE + n) = __floats2half2_rn(acc[j][0], acc[j][1]);
            *(__half2*)(Xs + (wr + fr + 8) * XS_STRIDE + n) = __floats2half2_rn(acc[j][2], acc[j][3]);
        }
        __syncthreads();

        // ---- LN1 + ReLU: read natural, write interleaved A-layout (in-place) ----
        {
            float4 b4 = ((const float4*)bs1)[lane];
            float4 g4 = ((const float4*)gs1)[lane];
            float4 e4 = ((const float4*)es1)[lane];
            #pragma unroll
            for (int rr = 0; rr < 8; ++rr) {
                int lrow = warp * 8 + rr;
                __half* R = Xs + lrow * XS_STRIDE;
                const __half2* qq2 = (const __half2*)(R + lane * 4);
                float2 f0 = __half22float2(qq2[0]);
                float2 f1 = __half22float2(qq2[1]);
                float a0 = f0.x + b4.x, a1 = f0.y + b4.y, a2 = f1.x + b4.z, a3 = f1.y + b4.w;
                float s = a0 + a1 + a2 + a3;
                float q = a0 * a0 + a1 * a1 + a2 * a2 + a3 * a3;
                #pragma unroll
                for (int off = 16; off > 0; off >>= 1) {
                    s += __shfl_xor_sync(0xFFFFFFFFu, s, off);
                    q += __shfl_xor_sync(0xFFFFFFFFu, q, off);
                }
                float mu   = s * (1.0f / 128.0f);
                float var  = q * (1.0f / 128.0f) - mu * mu;
                float rstd = rsqrtf(var + 1e-5f);
                float o0 = fmaxf(0.f, (a0 - mu) * rstd * g4.x + e4.x);
                float o1 = fmaxf(0.f, (a1 - mu) * rstd * g4.y + e4.y);
                float o2 = fmaxf(0.f, (a2 - mu) * rstd * g4.z + e4.z);
                float o3 = fmaxf(0.f, (a3 - mu) * rstd * g4.w + e4.w);
                int a = (lane & 1) * 8 + (lane & 2);
                __half* p = R + (lane >> 2) * 16 + a;
                *(__half2*)p       = __floats2half2_rn(o0, o1);
                *(__half2*)(p + 4) = __floats2half2_rn(o2, o3);
            }
        }
        __syncthreads();

        // ================= pass 2: Y @ W2 =================
        #pragma unroll
        for (int j = 0; j < 8; ++j) {
            acc[j][0] = 0.f; acc[j][1] = 0.f; acc[j][2] = 0.f; acc[j][3] = 0.f;
        }
        #pragma unroll
        for (int s = 0; s < 8; ++s) {
            uint2 av0 = *(const uint2*)(Xs + (wr + fr)     * XS_STRIDE + s * 16 + qd * 4);
            uint2 av1 = *(const uint2*)(Xs + (wr + fr + 8) * XS_STRIDE + s * 16 + qd * 4);
            #pragma unroll
            for (int j = 0; j < 8; ++j) {
                uint2 bv = *(const uint2*)(Ws2 + ((s * 128) + wc + j * 8 + fr) * 16 + qd * 4);
                asm volatile(
                    "mma.sync.aligned.m16n8k16.row.col.f32.f16.f16.f32 "
                    "{%0,%1,%2,%3}, {%4,%5,%6,%7}, {%8,%9}, {%0,%1,%2,%3};"
                    : "+f"(acc[j][0]), "+f"(acc[j][1]), "+f"(acc[j][2]), "+f"(acc[j][3])
                    : "r"(av0.x), "r"(av1.x), "r"(av0.y), "r"(av1.y),
                      "r"(bv.x), "r"(bv.y));
            }
        }
        __syncthreads();
        #pragma unroll
        for (int j = 0; j < 8; ++j) {
            int n = wc + j * 8 + qd * 2;
            *(__half2*)(Xs + (wr + fr)     * XS_STRIDE + n) = __floats2half2_rn(acc[j][0], acc[j][1]);
            *(__half2*)(Xs + (wr + fr + 8) * XS_STRIDE + n) = __floats2half2_rn(acc[j][2], acc[j][3]);
        }
        __syncthreads();

        // ---- LN2 + ReLU -> gmem (fp32 + fp16 copy) ----
        {
            float4 b4 = ((const float4*)bs2)[lane];
            float4 g4 = ((const float4*)gs2)[lane];
            float4 e4 = ((const float4*)es2)[lane];
            #pragma unroll
            for (int rr = 0; rr < 8; ++rr) {
                int lrow = warp * 8 + rr;
                int grow = rowBlk + lrow;
                const __half2* qq2 = (const __half2*)(Xs + lrow * XS_STRIDE + lane * 4);
                float2 f0 = __half22float2(qq2[0]);
                float2 f1 = __half22float2(qq2[1]);
                float a0 = f0.x + b4.x, a1 = f0.y + b4.y, a2 = f1.x + b4.z, a3 = f1.y + b4.w;
                float s = a0 + a1 + a2 + a3;
                float q = a0 * a0 + a1 * a1 + a2 * a2 + a3 * a3;
                #pragma unroll
                for (int off = 16; off > 0; off >>= 1) {
                    s += __shfl_xor_sync(0xFFFFFFFFu, s, off);
                    q += __shfl_xor_sync(0xFFFFFFFFu, q, off);
                }
                float mu   = s * (1.0f / 128.0f);
                float var  = q * (1.0f / 128.0f) - mu * mu;
                float rstd = rsqrtf(var + 1e-5f);
                float4 o;
                o.x = fmaxf(0.f, (a0 - mu) * rstd * g4.x + e4.x);
                o.y = fmaxf(0.f, (a1 - mu) * rstd * g4.y + e4.y);
                o.z = fmaxf(0.f, (a2 - mu) * rstd * g4.z + e4.z);
                o.w = fmaxf(0.f, (a3 - mu) * rstd * g4.w + e4.w);
                if (grow < nrows) {
                    *(float4*)(out + (size_t)grow * DF + lane * 4) = o;
                    __half2 p2[2];
                    p2[0] = __floats2half2_rn(o.x, o.y);
                    p2[1] = __floats2half2_rn(o.z, o.w);
                    *(float2*)(out16 + (size_t)grow * DF + lane * 4) = *(float2*)p2;
                }
            }
        }
        __syncthreads();
    }
}

// ---------------------------------------------------------------------------
__global__ void pool_kernel(const float* __restrict__ h, const int* __restrict__ gid,
                            float* __restrict__ pool, int N) {
    int c  = threadIdx.x;
    int n0 = blockIdx.x * 128;
    if (n0 >= N) return;
    int curg = __ldg(gid + n0);
    float acc = 0.f;
    #pragma unroll 4
    for (int i = 0; i < 128; ++i) {
        int n = n0 + i;
        if (n >= N) break;
        int g = __ldg(gid + n);
        if (g != curg) {
            atomicAdd(&pool[(size_t)curg * DF + c], acc);
            acc = 0.f;
            curg = g;
        }
        acc += __ldg(h + (size_t)n * DF + c);
    }
    atomicAdd(&pool[(size_t)curg * DF + c], acc);
}

// ---------------------------------------------------------------------------
__global__ void head_kernel(const float* __restrict__ pool, const float* __restrict__ desc,
                            const float* __restrict__ fc1W, const float* __restrict__ fc1b,
                            const float* __restrict__ n1g, const float* __restrict__ n1b,
                            const float* __restrict__ fc2W, const float* __restrict__ fc2b,
                            float* __restrict__ out, int X, int C) {
    int g = blockIdx.x;
    int t = threadIdx.x;
    int warp = t >> 5, lane = t & 31;

    __shared__ float xin[DF + 64];
    __shared__ float ss[4], qq[4];

    xin[t] = pool[(size_t)g * DF + t];
    if (t < X) xin[DF + t] = desc[(size_t)g * X + t];
    __syncthreads();

    int K = DF + X;
    float acc = fc1b[t];
    for (int k = 0; k < K; ++k)
        acc = fmaf(xin[k], __ldg(fc1W + (size_t)k * DF + t), acc);

    float s = acc, q = acc * acc;
    #pragma unroll
    for (int off = 16; off > 0; off >>= 1) {
        s += __shfl_xor_sync(0xFFFFFFFFu, s, off);
        q += __shfl_xor_sync(0xFFFFFFFFu, q, off);
    }
    if (lane == 0) { ss[warp] = s; qq[warp] = q; }
    __syncthreads();
    s = ss[0] + ss[1] + ss[2] + ss[3];
    q = qq[0] + qq[1] + qq[2] + qq[3];
    float mu   = s * (1.0f / 128.0f);
    float var  = q * (1.0f / 128.0f) - mu * mu;
    float rstd = rsqrtf(var + 1e-5f);
    float y = fmaxf(0.f, (acc - mu) * rstd * n1g[t] + n1b[t]);

    for (int c = 0; c < C; ++c) {
        float p = y * __ldg(fc2W + (size_t)t * C + c);
        #pragma unroll
        for (int off = 16; off > 0; off >>= 1)
            p += __shfl_xor_sync(0xFFFFFFFFu, p, off);
        __syncthreads();
        if (lane == 0) ss[warp] = p;
        __syncthreads();
        if (t == 0) out[(size_t)g * C + c] = ss[0] + ss[1] + ss[2] + ss[3] + fc2b[c];
    }
}

// ---------------------------------------------------------------------------
extern "C" void kernel_launch(void* const* d_in, const int* in_sizes, int n_in,
                              void* d_out, int out_size) {
    const float* h    = (const float*)d_in[0];
    const float* desc = (const float*)d_in[1];
    const int*   src  = (const int*)d_in[2];
    const int*   dst  = (const int*)d_in[3];
    const int*   gid  = (const int*)d_in[4];
    const float* W1   = (const float*)d_in[5];
    const float* b1   = (const float*)d_in[6];
    const float* g1   = (const float*)d_in[7];
    const float* be1  = (const float*)d_in[8];
    const float* W2   = (const float*)d_in[9];
    const float* b2   = (const float*)d_in[10];
    const float* eps  = (const float*)d_in[11];
    const float* ng   = (const float*)d_in[12];
    const float* nb   = (const float*)d_in[13];
    const float* fc1W = (const float*)d_in[14];
    const float* fc1b = (const float*)d_in[15];
    const float* n1g  = (const float*)d_in[16];
    const float* n1b  = (const float*)d_in[17];
    const float* fc2W = (const float*)d_in[18];
    const float* fc2b = (const float*)d_in[19];
    float* out = (float*)d_out;

    int N = in_sizes[0] / DF;
    int E = in_sizes[2];
    int L = in_sizes[11];
    int X = in_sizes[14] / DF - DF;
    if (X <= 0) X = 16;
    int G = in_sizes[1] / X;
    int C = in_sizes[18] / DF;
    if (C <= 0) C = 1;
    if (N > NMAX) N = NMAX;
    if (G > GMAX) G = GMAX;
    if (E > EMAX) E = EMAX;

    float *bufA, *bufC, *pool;
    __half* h16;
    int *degp, *rowptr, *cursor, *csrc, *bsum;
    cudaGetSymbolAddress((void**)&bufA, g_bufA);
    cudaGetSymbolAddress((void**)&bufC, g_bufC);
    cudaGetSymbolAddress((void**)&h16,  g_h16);
    cudaGetSymbolAddress((void**)&pool, g_pool);
    cudaGetSymbolAddress((void**)&degp, g_deg);
    cudaGetSymbolAddress((void**)&rowptr, g_rowptr);
    cudaGetSymbolAddress((void**)&cursor, g_cursor);
    cudaGetSymbolAddress((void**)&csrc, g_csrc);
    cudaGetSymbolAddress((void**)&bsum, g_bsum);

    const int SMEM_BYTES = (2 * 128 * 128 + 128 * XS_STRIDE) * 2 + 6 * DF * 4; // 105,472
    cudaFuncSetAttribute(layer_fused,
                         cudaFuncAttributeMaxDynamicSharedMemorySize, SMEM_BYTES);

    // --- CSR build + fp16 convert of input h (once per launch) ---
    int nb_scan = (N + 1023) / 1024;
    cudaMemsetAsync(degp, 0, (size_t)N * sizeof(int));
    deg_kernel<<<(E + 255) / 256, 256>>>(dst, degp, E);
    scan1_kernel<<<nb_scan, 1024>>>(degp, rowptr, bsum, N);
    scan2_kernel<<<1, 32>>>(bsum, nb_scan);
    scan3_kernel<<<nb_scan, 1024>>>(rowptr, bsum, N, E);
    cudaMemcpyAsync(cursor, rowptr, (size_t)N * sizeof(int), cudaMemcpyDeviceToDevice);
    scatter_kernel<<<(E + 255) / 256, 256>>>(src, dst, cursor, csrc, E);
    int nd4 = N * (DF / 4);
    cvt16_kernel<<<(nd4 + 255) / 256, 256>>>(h, h16, nd4);

    int ntiles = (N + 127) / 128;
    int fgrid = ntiles < 296 ? ntiles : 296;
    int agg_grid = (N * 32 + 255) / 256;

    const float* hcur = h;
    for (int l = 0; l < L; ++l) {
        agg_kernel<<<agg_grid, 256>>>(h16, rowptr, csrc, bufA, N);
        layer_fused<<<fgrid, 512, SMEM_BYTES>>>(
            bufA, hcur, eps, l,
            W1 + (size_t)l * DF * DF, b1 + (size_t)l * DF,
            g1 + (size_t)l * DF, be1 + (size_t)l * DF,
            W2 + (size_t)l * DF * DF, b2 + (size_t)l * DF,
            ng + (size_t)l * DF, nb + (size_t)l * DF,
            bufC, h16, N, ntiles);
        hcur = bufC;
    }

    cudaMemsetAsync(pool, 0, (size_t)G * DF * sizeof(float));
    pool_kernel<<<(N + 127) / 128, 128>>>(hcur, gid, pool, N);
    head_kernel<<<G, 128>>>(pool, desc, fc1W, fc1b, n1g, n1b, fc2W, fc2b, out, X, C);
}

// round 10
// speedup vs baseline: 1.1286x; 1.0311x over previous
#include <cuda_runtime.h>
#include <cuda_fp16.h>
#include <cstdint>

#define DF 128
#define NMAX 100000
#define EMAX 1600000
#define GMAX 1024

// persistent scratch (no allocations allowed)
__device__ float  g_bufA[(size_t)NMAX * DF];
__device__ float  g_bufC[(size_t)NMAX * DF];
__device__ __half g_h16[(size_t)NMAX * DF];
__device__ float  g_pool[(size_t)GMAX * DF];
__device__ int    g_deg[NMAX];
__device__ int    g_rowptr[NMAX + 1];
__device__ int    g_cursor[NMAX];
__device__ int    g_csrc[EMAX];
__device__ int    g_bsum[1024];

// ---------------------------------------------------------------------------
// CSR build: degree histogram -> exclusive scan -> scatter
__global__ void deg_kernel(const int* __restrict__ dst, int* __restrict__ deg, int E) {
    int i = blockIdx.x * blockDim.x + threadIdx.x;
    if (i < E) atomicAdd(&deg[__ldg(dst + i)], 1);
}

__global__ void scan1_kernel(const int* __restrict__ deg, int* __restrict__ rowptr,
                             int* __restrict__ bsum, int N) {
    __shared__ int sh[1024];
    int tid = threadIdx.x;
    int i = blockIdx.x * 1024 + tid;
    int v = (i < N) ? deg[i] : 0;
    sh[tid] = v;
    __syncthreads();
    #pragma unroll
    for (int off = 1; off < 1024; off <<= 1) {
        int t = (tid >= off) ? sh[tid - off] : 0;
        __syncthreads();
        sh[tid] += t;
        __syncthreads();
    }
    if (i < N) rowptr[i] = sh[tid] - v;
    if (tid == 1023) bsum[blockIdx.x] = sh[1023];
}

__global__ void scan2_kernel(int* __restrict__ bsum, int nb) {
    if (threadIdx.x == 0 && blockIdx.x == 0) {
        int acc = 0;
        for (int i = 0; i < nb; ++i) {
            int v = bsum[i];
            bsum[i] = acc;
            acc += v;
        }
    }
}

__global__ void scan3_kernel(int* __restrict__ rowptr, const int* __restrict__ bsum,
                             int N, int E) {
    int i = blockIdx.x * 1024 + threadIdx.x;
    if (i < N) rowptr[i] += bsum[blockIdx.x];
    if (i == 0) rowptr[N] = E;
}

__global__ void scatter_kernel(const int* __restrict__ src, const int* __restrict__ dst,
                               int* __restrict__ cursor, int* __restrict__ csrc, int E) {
    int i = blockIdx.x * blockDim.x + threadIdx.x;
    if (i < E) {
        int pos = atomicAdd(&cursor[__ldg(dst + i)], 1);
        csrc[pos] = __ldg(src + i);
    }
}

// ---------------------------------------------------------------------------
// fp32 -> fp16 convert (initial h only)
__global__ void cvt16_kernel(const float* __restrict__ src, __half* __restrict__ dst, int n4) {
    int i = blockIdx.x * blockDim.x + threadIdx.x;
    if (i < n4) {
        float4 v = *(const float4*)(src + i * 4);
        __half2 p2[2];
        p2[0] = __floats2half2_rn(v.x, v.y);
        p2[1] = __floats2half2_rn(v.z, v.w);
        *(float2*)(dst + i * 4) = *(float2*)p2;
    }
}

// ---------------------------------------------------------------------------
__device__ __forceinline__ void acc8(float* acc, uint4 p) {
    float2 f0 = __half22float2(*(__half2*)&p.x);
    float2 f1 = __half22float2(*(__half2*)&p.y);
    float2 f2 = __half22float2(*(__half2*)&p.z);
    float2 f3 = __half22float2(*(__half2*)&p.w);
    acc[0] += f0.x; acc[1] += f0.y;
    acc[2] += f1.x; acc[3] += f1.y;
    acc[4] += f2.x; acc[5] += f2.y;
    acc[6] += f3.x; acc[7] += f3.y;
}

// Pull aggregation: 2 nodes per warp (one per half-warp). Each lane loads
// 16B (8 halfs) per neighbor -> 16 LDG.128 per edge row (2x fewer issues
// than the LDG.64 variant). fp32 accumulation, neighbor unroll x4 (MLP=4).
__global__ void agg_kernel(const __half* __restrict__ h16, const int* __restrict__ rowptr,
                           const int* __restrict__ csrc, float* __restrict__ agg, int N) {
    int w    = (blockIdx.x * blockDim.x + threadIdx.x) >> 5;
    int lane = threadIdx.x & 31;
    int hl   = lane & 15;
    int v    = w * 2 + (lane >> 4);
    if (v >= N) return;
    int beg = __ldg(rowptr + v), end = __ldg(rowptr + v + 1);
    float acc[8] = {0.f, 0.f, 0.f, 0.f, 0.f, 0.f, 0.f, 0.f};
    int i = beg;
    for (; i + 4 <= end; i += 4) {
        int u0 = __ldg(csrc + i),     u1 = __ldg(csrc + i + 1);
        int u2 = __ldg(csrc + i + 2), u3 = __ldg(csrc + i + 3);
        uint4 p0 = *(const uint4*)(h16 + (size_t)u0 * DF + hl * 8);
        uint4 p1 = *(const uint4*)(h16 + (size_t)u1 * DF + hl * 8);
        uint4 p2 = *(const uint4*)(h16 + (size_t)u2 * DF + hl * 8);
        uint4 p3 = *(const uint4*)(h16 + (size_t)u3 * DF + hl * 8);
        acc8(acc, p0); acc8(acc, p1); acc8(acc, p2); acc8(acc, p3);
    }
    for (; i < end; ++i) {
        int u = __ldg(csrc + i);
        uint4 p = *(const uint4*)(h16 + (size_t)u * DF + hl * 8);
        acc8(acc, p);
    }
    float* o = agg + (size_t)v * DF + hl * 8;
    *(float4*)o       = make_float4(acc[0], acc[1], acc[2], acc[3]);
    *(float4*)(o + 4) = make_float4(acc[4], acc[5], acc[6], acc[7]);
}

// ---------------------------------------------------------------------------
// Fully fused GIN layer MLP with fp16 HMMA m16n8k16, fp32 accum.
// 512 threads (16 warps), warp tile 16x64, occupancy 2 (smem ~103KB).
#define XS_STRIDE 144

__global__ void __launch_bounds__(512, 2)
layer_fused(const float* __restrict__ x, const float* __restrict__ hres,
            const float* __restrict__ epsArr, int layer,
            const float* __restrict__ W1, const float* __restrict__ b1,
            const float* __restrict__ g1, const float* __restrict__ be1,
            const float* __restrict__ W2, const float* __restrict__ b2,
            const float* __restrict__ ng, const float* __restrict__ nb,
            float* __restrict__ out, __half* __restrict__ out16,
            int nrows, int ntiles) {
    extern __shared__ __align__(16) char smraw[];
    __half* Ws1 = (__half*)smraw;                       // 128*128 halfs = 32KB
    __half* Ws2 = Ws1 + 128 * 128;                      // 32KB
    __half* Xs  = Ws2 + 128 * 128;                      // 128*144 halfs
    float*  prm = (float*)(Xs + 128 * XS_STRIDE);       // 6*128 floats
    float* bs1 = prm, *gs1 = prm + 128, *es1 = prm + 256;
    float* bs2 = prm + 384, *gs2 = prm + 512, *es2 = prm + 640;

    int tid  = threadIdx.x;
    int lane = tid & 31, warp = tid >> 5;

    // Stage W1/W2 as half, interleaved: Ws[(s*128+n)*16 + pos(k&15)]
    for (int idx = tid; idx < 4096; idx += 512) {
        int k  = idx >> 5;
        int n4 = idx & 31;
        int s  = k >> 4, kq = k & 15;
        int pos = (kq & 1) | (((kq >> 3) & 1) << 1) | (((kq >> 1) & 3) << 2);
        size_t go = (size_t)k * DF + n4 * 4;
        float4 wa = *(const float4*)(W1 + go);
        float4 wb = *(const float4*)(W2 + go);
        int base = ((s * 128) + n4 * 4) * 16 + pos;
        Ws1[base]      = __float2half(wa.x);
        Ws1[base + 16] = __float2half(wa.y);
        Ws1[base + 32] = __float2half(wa.z);
        Ws1[base + 48] = __float2half(wa.w);
        Ws2[base]      = __float2half(wb.x);
        Ws2[base + 16] = __float2half(wb.y);
        Ws2[base + 32] = __float2half(wb.z);
        Ws2[base + 48] = __float2half(wb.w);
    }
    if (tid < DF) {
        bs1[tid] = b1[tid]; gs1[tid] = g1[tid]; es1[tid] = be1[tid];
        bs2[tid] = b2[tid]; gs2[tid] = ng[tid]; es2[tid] = nb[tid];
    }

    float escale = 1.0f + epsArr[layer];

    int wr = (warp & 7) * 16;
    int wc = (warp >> 3) * 64;
    int fr = lane >> 2;
    int qd = lane & 3;

    __syncthreads();

    for (int tile = blockIdx.x; tile < ntiles; tile += gridDim.x) {
        int rowBlk = tile * 128;

        // ---- stage X + residual -> half, interleaved A-layout ----
        for (int idx = tid; idx < 128 * 32; idx += 512) {
            int r = idx >> 5, c4 = idx & 31;
            int row = rowBlk + r;
            float4 v = make_float4(0.f, 0.f, 0.f, 0.f);
            if (row < nrows) {
                v = *(const float4*)(x + (size_t)row * DF + c4 * 4);
                float4 hv = *(const float4*)(hres + (size_t)row * DF + c4 * 4);
                v.x = fmaf(escale, hv.x, v.x);
                v.y = fmaf(escale, hv.y, v.y);
                v.z = fmaf(escale, hv.z, v.z);
                v.w = fmaf(escale, hv.w, v.w);
            }
            int a = (c4 & 1) * 8 + (c4 & 2);
            __half* p = Xs + r * XS_STRIDE + (c4 >> 2) * 16 + a;
            *(__half2*)p       = __floats2half2_rn(v.x, v.y);
            *(__half2*)(p + 4) = __floats2half2_rn(v.z, v.w);
        }
        __syncthreads();

        float acc[8][4];

        // ================= pass 1: X @ W1 =================
        #pragma unroll
        for (int j = 0; j < 8; ++j) {
            acc[j][0] = 0.f; acc[j][1] = 0.f; acc[j][2] = 0.f; acc[j][3] = 0.f;
        }
        #pragma unroll
        for (int s = 0; s < 8; ++s) {
            uint2 av0 = *(const uint2*)(Xs + (wr + fr)     * XS_STRIDE + s * 16 + qd * 4);
            uint2 av1 = *(const uint2*)(Xs + (wr + fr + 8) * XS_STRIDE + s * 16 + qd * 4);
            #pragma unroll
            for (int j = 0; j < 8; ++j) {
                uint2 bv = *(const uint2*)(Ws1 + ((s * 128) + wc + j * 8 + fr) * 16 + qd * 4);
                asm volatile(
                    "mma.sync.aligned.m16n8k16.row.col.f32.f16.f16.f32 "
                    "{%0,%1,%2,%3}, {%4,%5,%6,%7}, {%8,%9}, {%0,%1,%2,%3};"
                    : "+f"(acc[j][0]), "+f"(acc[j][1]), "+f"(acc[j][2]), "+f"(acc[j][3])
                    : "r"(av0.x), "r"(av1.x), "r"(av0.y), "r"(av1.y),
                      "r"(bv.x), "r"(bv.y));
            }
        }
        __syncthreads();
        #pragma unroll
        for (int j = 0; j < 8; ++j) {
            int n = wc + j * 8 + qd * 2;
            *(__half2*)(Xs + (wr + fr)     * XS_STRIDE + n) = __floats2half2_rn(acc[j][0], acc[j][1]);
            *(__half2*)(Xs + (wr + fr + 8) * XS_STRIDE + n) = __floats2half2_rn(acc[j][2], acc[j][3]);
        }
        __syncthreads();

        // ---- LN1 + ReLU: read natural, write interleaved A-layout (in-place) ----
        {
            float4 b4 = ((const float4*)bs1)[lane];
            float4 g4 = ((const float4*)gs1)[lane];
            float4 e4 = ((const float4*)es1)[lane];
            #pragma unroll
            for (int rr = 0; rr < 8; ++rr) {
                int lrow = warp * 8 + rr;
                __half* R = Xs + lrow * XS_STRIDE;
                const __half2* qq2 = (const __half2*)(R + lane * 4);
                float2 f0 = __half22float2(qq2[0]);
                float2 f1 = __half22float2(qq2[1]);
                float a0 = f0.x + b4.x, a1 = f0.y + b4.y, a2 = f1.x + b4.z, a3 = f1.y + b4.w;
                float s = a0 + a1 + a2 + a3;
                float q = a0 * a0 + a1 * a1 + a2 * a2 + a3 * a3;
                #pragma unroll
                for (int off = 16; off > 0; off >>= 1) {
                    s += __shfl_xor_sync(0xFFFFFFFFu, s, off);
                    q += __shfl_xor_sync(0xFFFFFFFFu, q, off);
                }
                float mu   = s * (1.0f / 128.0f);
                float var  = q * (1.0f / 128.0f) - mu * mu;
                float rstd = rsqrtf(var + 1e-5f);
                float o0 = fmaxf(0.f, (a0 - mu) * rstd * g4.x + e4.x);
                float o1 = fmaxf(0.f, (a1 - mu) * rstd * g4.y + e4.y);
                float o2 = fmaxf(0.f, (a2 - mu) * rstd * g4.z + e4.z);
                float o3 = fmaxf(0.f, (a3 - mu) * rstd * g4.w + e4.w);
                int a = (lane & 1) * 8 + (lane & 2);
                __half* p = R + (lane >> 2) * 16 + a;
                *(__half2*)p       = __floats2half2_rn(o0, o1);
                *(__half2*)(p + 4) = __floats2half2_rn(o2, o3);
            }
        }
        __syncthreads();

        // ================= pass 2: Y @ W2 =================
        #pragma unroll
        for (int j = 0; j < 8; ++j) {
            acc[j][0] = 0.f; acc[j][1] = 0.f; acc[j][2] = 0.f; acc[j][3] = 0.f;
        }
        #pragma unroll
        for (int s = 0; s < 8; ++s) {
            uint2 av0 = *(const uint2*)(Xs + (wr + fr)     * XS_STRIDE + s * 16 + qd * 4);
            uint2 av1 = *(const uint2*)(Xs + (wr + fr + 8) * XS_STRIDE + s * 16 + qd * 4);
            #pragma unroll
            for (int j = 0; j < 8; ++j) {
                uint2 bv = *(const uint2*)(Ws2 + ((s * 128) + wc + j * 8 + fr) * 16 + qd * 4);
                asm volatile(
                    "mma.sync.aligned.m16n8k16.row.col.f32.f16.f16.f32 "
                    "{%0,%1,%2,%3}, {%4,%5,%6,%7}, {%8,%9}, {%0,%1,%2,%3};"
                    : "+f"(acc[j][0]), "+f"(acc[j][1]), "+f"(acc[j][2]), "+f"(acc[j][3])
                    : "r"(av0.x), "r"(av1.x), "r"(av0.y), "r"(av1.y),
                      "r"(bv.x), "r"(bv.y));
            }
        }
        __syncthreads();
        #pragma unroll
        for (int j = 0; j < 8; ++j) {
            int n = wc + j * 8 + qd * 2;
            *(__half2*)(Xs + (wr + fr)     * XS_STRIDE + n) = __floats2half2_rn(acc[j][0], acc[j][1]);
            *(__half2*)(Xs + (wr + fr + 8) * XS_STRIDE + n) = __floats2half2_rn(acc[j][2], acc[j][3]);
        }
        __syncthreads();

        // ---- LN2 + ReLU -> gmem (fp32 + fp16 copy) ----
        {
            float4 b4 = ((const float4*)bs2)[lane];
            float4 g4 = ((const float4*)gs2)[lane];
            float4 e4 = ((const float4*)es2)[lane];
            #pragma unroll
            for (int rr = 0; rr < 8; ++rr) {
                int lrow = warp * 8 + rr;
                int grow = rowBlk + lrow;
                const __half2* qq2 = (const __half2*)(Xs + lrow * XS_STRIDE + lane * 4);
                float2 f0 = __half22float2(qq2[0]);
                float2 f1 = __half22float2(qq2[1]);
                float a0 = f0.x + b4.x, a1 = f0.y + b4.y, a2 = f1.x + b4.z, a3 = f1.y + b4.w;
                float s = a0 + a1 + a2 + a3;
                float q = a0 * a0 + a1 * a1 + a2 * a2 + a3 * a3;
                #pragma unroll
                for (int off = 16; off > 0; off >>= 1) {
                    s += __shfl_xor_sync(0xFFFFFFFFu, s, off);
                    q += __shfl_xor_sync(0xFFFFFFFFu, q, off);
                }
                float mu   = s * (1.0f / 128.0f);
                float var  = q * (1.0f / 128.0f) - mu * mu;
                float rstd = rsqrtf(var + 1e-5f);
                float4 o;
                o.x = fmaxf(0.f, (a0 - mu) * rstd * g4.x + e4.x);
                o.y = fmaxf(0.f, (a1 - mu) * rstd * g4.y + e4.y);
                o.z = fmaxf(0.f, (a2 - mu) * rstd * g4.z + e4.z);
                o.w = fmaxf(0.f, (a3 - mu) * rstd * g4.w + e4.w);
                if (grow < nrows) {
                    *(float4*)(out + (size_t)grow * DF + lane * 4) = o;
                    __half2 p2[2];
                    p2[0] = __floats2half2_rn(o.x, o.y);
                    p2[1] = __floats2half2_rn(o.z, o.w);
                    *(float2*)(out16 + (size_t)grow * DF + lane * 4) = *(float2*)p2;
                }
            }
        }
        __syncthreads();
    }
}

// ---------------------------------------------------------------------------
__global__ void pool_kernel(const float* __restrict__ h, const int* __restrict__ gid,
                            float* __restrict__ pool, int N) {
    int c  = threadIdx.x;
    int n0 = blockIdx.x * 128;
    if (n0 >= N) return;
    int curg = __ldg(gid + n0);
    float acc = 0.f;
    #pragma unroll 4
    for (int i = 0; i < 128; ++i) {
        int n = n0 + i;
        if (n >= N) break;
        int g = __ldg(gid + n);
        if (g != curg) {
            atomicAdd(&pool[(size_t)curg * DF + c], acc);
            acc = 0.f;
            curg = g;
        }
        acc += __ldg(h + (size_t)n * DF + c);
    }
    atomicAdd(&pool[(size_t)curg * DF + c], acc);
}

// ---------------------------------------------------------------------------
__global__ void head_kernel(const float* __restrict__ pool, const float* __restrict__ desc,
                            const float* __restrict__ fc1W, const float* __restrict__ fc1b,
                            const float* __restrict__ n1g, const float* __restrict__ n1b,
                            const float* __restrict__ fc2W, const float* __restrict__ fc2b,
                            float* __restrict__ out, int X, int C) {
    int g = blockIdx.x;
    int t = threadIdx.x;
    int warp = t >> 5, lane = t & 31;

    __shared__ float xin[DF + 64];
    __shared__ float ss[4], qq[4];

    xin[t] = pool[(size_t)g * DF + t];
    if (t < X) xin[DF + t] = desc[(size_t)g * X + t];
    __syncthreads();

    int K = DF + X;
    float acc = fc1b[t];
    for (int k = 0; k < K; ++k)
        acc = fmaf(xin[k], __ldg(fc1W + (size_t)k * DF + t), acc);

    float s = acc, q = acc * acc;
    #pragma unroll
    for (int off = 16; off > 0; off >>= 1) {
        s += __shfl_xor_sync(0xFFFFFFFFu, s, off);
        q += __shfl_xor_sync(0xFFFFFFFFu, q, off);
    }
    if (lane == 0) { ss[warp] = s; qq[warp] = q; }
    __syncthreads();
    s = ss[0] + ss[1] + ss[2] + ss[3];
    q = qq[0] + qq[1] + qq[2] + qq[3];
    float mu   = s * (1.0f / 128.0f);
    float var  = q * (1.0f / 128.0f) - mu * mu;
    float rstd = rsqrtf(var + 1e-5f);
    float y = fmaxf(0.f, (acc - mu) * rstd * n1g[t] + n1b[t]);

    for (int c = 0; c < C; ++c) {
        float p = y * __ldg(fc2W + (size_t)t * C + c);
        #pragma unroll
        for (int off = 16; off > 0; off >>= 1)
            p += __shfl_xor_sync(0xFFFFFFFFu, p, off);
        __syncthreads();
        if (lane == 0) ss[warp] = p;
        __syncthreads();
        if (t == 0) out[(size_t)g * C + c] = ss[0] + ss[1] + ss[2] + ss[3] + fc2b[c];
    }
}

// ---------------------------------------------------------------------------
extern "C" void kernel_launch(void* const* d_in, const int* in_sizes, int n_in,
                              void* d_out, int out_size) {
    const float* h    = (const float*)d_in[0];
    const float* desc = (const float*)d_in[1];
    const int*   src  = (const int*)d_in[2];
    const int*   dst  = (const int*)d_in[3];
    const int*   gid  = (const int*)d_in[4];
    const float* W1   = (const float*)d_in[5];
    const float* b1   = (const float*)d_in[6];
    const float* g1   = (const float*)d_in[7];
    const float* be1  = (const float*)d_in[8];
    const float* W2   = (const float*)d_in[9];
    const float* b2   = (const float*)d_in[10];
    const float* eps  = (const float*)d_in[11];
    const float* ng   = (const float*)d_in[12];
    const float* nb   = (const float*)d_in[13];
    const float* fc1W = (const float*)d_in[14];
    const float* fc1b = (const float*)d_in[15];
    const float* n1g  = (const float*)d_in[16];
    const float* n1b  = (const float*)d_in[17];
    const float* fc2W = (const float*)d_in[18];
    const float* fc2b = (const float*)d_in[19];
    float* out = (float*)d_out;

    int N = in_sizes[0] / DF;
    int E = in_sizes[2];
    int L = in_sizes[11];
    int X = in_sizes[14] / DF - DF;
    if (X <= 0) X = 16;
    int G = in_sizes[1] / X;
    int C = in_sizes[18] / DF;
    if (C <= 0) C = 1;
    if (N > NMAX) N = NMAX;
    if (G > GMAX) G = GMAX;
    if (E > EMAX) E = EMAX;

    float *bufA, *bufC, *pool;
    __half* h16;
    int *degp, *rowptr, *cursor, *csrc, *bsum;
    cudaGetSymbolAddress((void**)&bufA, g_bufA);
    cudaGetSymbolAddress((void**)&bufC, g_bufC);
    cudaGetSymbolAddress((void**)&h16,  g_h16);
    cudaGetSymbolAddress((void**)&pool, g_pool);
    cudaGetSymbolAddress((void**)&degp, g_deg);
    cudaGetSymbolAddress((void**)&rowptr, g_rowptr);
    cudaGetSymbolAddress((void**)&cursor, g_cursor);
    cudaGetSymbolAddress((void**)&csrc, g_csrc);
    cudaGetSymbolAddress((void**)&bsum, g_bsum);

    const int SMEM_BYTES = (2 * 128 * 128 + 128 * XS_STRIDE) * 2 + 6 * DF * 4; // 105,472
    cudaFuncSetAttribute(layer_fused,
                         cudaFuncAttributeMaxDynamicSharedMemorySize, SMEM_BYTES);

    // --- CSR build + fp16 convert of input h (once per launch) ---
    int nb_scan = (N + 1023) / 1024;
    cudaMemsetAsync(degp, 0, (size_t)N * sizeof(int));
    deg_kernel<<<(E + 255) / 256, 256>>>(dst, degp, E);
    scan1_kernel<<<nb_scan, 1024>>>(degp, rowptr, bsum, N);
    scan2_kernel<<<1, 32>>>(bsum, nb_scan);
    scan3_kernel<<<nb_scan, 1024>>>(rowptr, bsum, N, E);
    cudaMemcpyAsync(cursor, rowptr, (size_t)N * sizeof(int), cudaMemcpyDeviceToDevice);
    scatter_kernel<<<(E + 255) / 256, 256>>>(src, dst, cursor, csrc, E);
    int nd4 = N * (DF / 4);
    cvt16_kernel<<<(nd4 + 255) / 256, 256>>>(h, h16, nd4);

    int ntiles = (N + 127) / 128;
    int fgrid = ntiles < 296 ? ntiles : 296;
    int aggwarps = (N + 1) / 2;
    int agg_grid = (aggwarps * 32 + 255) / 256;

    const float* hcur = h;
    for (int l = 0; l < L; ++l) {
        agg_kernel<<<agg_grid, 256>>>(h16, rowptr, csrc, bufA, N);
        layer_fused<<<fgrid, 512, SMEM_BYTES>>>(
            bufA, hcur, eps, l,
            W1 + (size_t)l * DF * DF, b1 + (size_t)l * DF,
            g1 + (size_t)l * DF, be1 + (size_t)l * DF,
            W2 + (size_t)l * DF * DF, b2 + (size_t)l * DF,
            ng + (size_t)l * DF, nb + (size_t)l * DF,
            bufC, h16, N, ntiles);
        hcur = bufC;
    }

    cudaMemsetAsync(pool, 0, (size_t)G * DF * sizeof(float));
    pool_kernel<<<(N + 127) / 128, 128>>>(hcur, gid, pool, N);
    head_kernel<<<G, 128>>>(pool, desc, fc1W, fc1b, n1g, n1b, fc2W, fc2b, out, X, C);
}

// round 12
// speedup vs baseline: 1.1418x; 1.0118x over previous
#include <cuda_runtime.h>
#include <cuda_fp16.h>
#include <cstdint>

#define DF 128
#define NMAX 100000
#define EMAX 1600000
#define GMAX 1024

// persistent scratch (no allocations allowed)
__device__ float  g_bufC[(size_t)NMAX * DF];
__device__ __half g_h16a[(size_t)NMAX * DF];
__device__ __half g_h16b[(size_t)NMAX * DF];
__device__ float  g_pool[(size_t)GMAX * DF];
__device__ int    g_deg[NMAX];
__device__ int    g_rowptr[NMAX + 1];
__device__ int    g_cursor[NMAX];
__device__ int    g_csrc[EMAX];
__device__ int    g_bsum[1024];

// ---------------------------------------------------------------------------
// CSR build: degree histogram -> exclusive scan -> scatter
__global__ void deg_kernel(const int* __restrict__ dst, int* __restrict__ deg, int E) {
    int i = blockIdx.x * blockDim.x + threadIdx.x;
    if (i < E) atomicAdd(&deg[__ldg(dst + i)], 1);
}

__global__ void scan1_kernel(const int* __restrict__ deg, int* __restrict__ rowptr,
                             int* __restrict__ bsum, int N) {
    __shared__ int sh[1024];
    int tid = threadIdx.x;
    int i = blockIdx.x * 1024 + tid;
    int v = (i < N) ? deg[i] : 0;
    sh[tid] = v;
    __syncthreads();
    #pragma unroll
    for (int off = 1; off < 1024; off <<= 1) {
        int t = (tid >= off) ? sh[tid - off] : 0;
        __syncthreads();
        sh[tid] += t;
        __syncthreads();
    }
    if (i < N) rowptr[i] = sh[tid] - v;
    if (tid == 1023) bsum[blockIdx.x] = sh[1023];
}

__global__ void scan2_kernel(int* __restrict__ bsum, int nb) {
    if (threadIdx.x == 0 && blockIdx.x == 0) {
        int acc = 0;
        for (int i = 0; i < nb; ++i) {
            int v = bsum[i];
            bsum[i] = acc;
            acc += v;
        }
    }
}

// also writes cursor (saves the memcpy launch)
__global__ void scan3_kernel(int* __restrict__ rowptr, const int* __restrict__ bsum,
                             int* __restrict__ cursor, int N, int E) {
    int i = blockIdx.x * 1024 + threadIdx.x;
    if (i < N) {
        int v = rowptr[i] + bsum[blockIdx.x];
        rowptr[i] = v;
        cursor[i] = v;
    }
    if (i == 0) rowptr[N] = E;
}

__global__ void scatter_kernel(const int* __restrict__ src, const int* __restrict__ dst,
                               int* __restrict__ cursor, int* __restrict__ csrc, int E) {
    int i = blockIdx.x * blockDim.x + threadIdx.x;
    if (i < E) {
        int pos = atomicAdd(&cursor[__ldg(dst + i)], 1);
        csrc[pos] = __ldg(src + i);
    }
}

// ---------------------------------------------------------------------------
// fp32 -> fp16 convert (initial h only)
__global__ void cvt16_kernel(const float* __restrict__ src, __half* __restrict__ dst, int n4) {
    int i = blockIdx.x * blockDim.x + threadIdx.x;
    if (i < n4) {
        float4 v = *(const float4*)(src + i * 4);
        __half2 p2[2];
        p2[0] = __floats2half2_rn(v.x, v.y);
        p2[1] = __floats2half2_rn(v.z, v.w);
        *(float2*)(dst + i * 4) = *(float2*)p2;
    }
}

// ---------------------------------------------------------------------------
__device__ __forceinline__ void acc8(float* acc, uint4 p) {
    float2 f0 = __half22float2(*(__half2*)&p.x);
    float2 f1 = __half22float2(*(__half2*)&p.y);
    float2 f2 = __half22float2(*(__half2*)&p.z);
    float2 f3 = __half22float2(*(__half2*)&p.w);
    acc[0] += f0.x; acc[1] += f0.y;
    acc[2] += f1.x; acc[3] += f1.y;
    acc[4] += f2.x; acc[5] += f2.y;
    acc[6] += f3.x; acc[7] += f3.y;
}

// ---------------------------------------------------------------------------
// Fully fused GIN layer: staging does the neighbor gather (from fp16 IN buf)
// + residual, then HMMA m16n8k16 MLP with fused LN+ReLU twice, writes fp32 +
// fp16 OUT buf (double-buffered -> no RAW race across tiles).
#define XS_STRIDE 144

__global__ void __launch_bounds__(512, 2)
layer_fused(const __half* __restrict__ hin16, const float* __restrict__ hres,
            const int* __restrict__ rowptr, const int* __restrict__ csrc,
            const float* __restrict__ epsArr, int layer,
            const float* __restrict__ W1, const float* __restrict__ b1,
            const float* __restrict__ g1, const float* __restrict__ be1,
            const float* __restrict__ W2, const float* __restrict__ b2,
            const float* __restrict__ ng, const float* __restrict__ nb,
            float* __restrict__ out, __half* __restrict__ out16,
            int nrows, int ntiles) {
    extern __shared__ __align__(16) char smraw[];
    __half* Ws1 = (__half*)smraw;                       // 128*128 halfs = 32KB
    __half* Ws2 = Ws1 + 128 * 128;                      // 32KB
    __half* Xs  = Ws2 + 128 * 128;                      // 128*144 halfs
    float*  prm = (float*)(Xs + 128 * XS_STRIDE);       // 6*128 floats
    float* bs1 = prm, *gs1 = prm + 128, *es1 = prm + 256;
    float* bs2 = prm + 384, *gs2 = prm + 512, *es2 = prm + 640;

    int tid  = threadIdx.x;
    int lane = tid & 31, warp = tid >> 5;

    // Stage W1/W2 as half, interleaved: Ws[(s*128+n)*16 + pos(k&15)]
    for (int idx = tid; idx < 4096; idx += 512) {
        int k  = idx >> 5;
        int n4 = idx & 31;
        int s  = k >> 4, kq = k & 15;
        int pos = (kq & 1) | (((kq >> 3) & 1) << 1) | (((kq >> 1) & 3) << 2);
        size_t go = (size_t)k * DF + n4 * 4;
        float4 wa = *(const float4*)(W1 + go);
        float4 wb = *(const float4*)(W2 + go);
        int base = ((s * 128) + n4 * 4) * 16 + pos;
        Ws1[base]      = __float2half(wa.x);
        Ws1[base + 16] = __float2half(wa.y);
        Ws1[base + 32] = __float2half(wa.z);
        Ws1[base + 48] = __float2half(wa.w);
        Ws2[base]      = __float2half(wb.x);
        Ws2[base + 16] = __float2half(wb.y);
        Ws2[base + 32] = __float2half(wb.z);
        Ws2[base + 48] = __float2half(wb.w);
    }
    if (tid < DF) {
        bs1[tid] = b1[tid]; gs1[tid] = g1[tid]; es1[tid] = be1[tid];
        bs2[tid] = b2[tid]; gs2[tid] = ng[tid]; es2[tid] = nb[tid];
    }

    float escale = 1.0f + epsArr[layer];

    int wr = (warp & 7) * 16;
    int wc = (warp >> 3) * 64;
    int fr = lane >> 2;
    int qd = lane & 3;
    int hw = lane >> 4;        // half-warp id
    int hl = lane & 15;        // lane within half-warp

    __syncthreads();

    for (int tile = blockIdx.x; tile < ntiles; tile += gridDim.x) {
        int rowBlk = tile * 128;

        // ---- stage: GIN aggregate (gather hin16 neighbors) + residual ----
        for (int rr = 0; rr < 4; ++rr) {
            int r   = warp * 8 + hw * 4 + rr;
            int row = rowBlk + r;
            float acc[8] = {0.f, 0.f, 0.f, 0.f, 0.f, 0.f, 0.f, 0.f};
            if (row < nrows) {
                int beg = __ldg(rowptr + row), end = __ldg(rowptr + row + 1);
                int i = beg;
                for (; i + 4 <= end; i += 4) {
                    int u0 = __ldg(csrc + i),     u1 = __ldg(csrc + i + 1);
                    int u2 = __ldg(csrc + i + 2), u3 = __ldg(csrc + i + 3);
                    uint4 p0 = *(const uint4*)(hin16 + (size_t)u0 * DF + hl * 8);
                    uint4 p1 = *(const uint4*)(hin16 + (size_t)u1 * DF + hl * 8);
                    uint4 p2 = *(const uint4*)(hin16 + (size_t)u2 * DF + hl * 8);
                    uint4 p3 = *(const uint4*)(hin16 + (size_t)u3 * DF + hl * 8);
                    acc8(acc, p0); acc8(acc, p1); acc8(acc, p2); acc8(acc, p3);
                }
                for (; i < end; ++i) {
                    int u = __ldg(csrc + i);
                    uint4 p = *(const uint4*)(hin16 + (size_t)u * DF + hl * 8);
                    acc8(acc, p);
                }
                float4 h0 = *(const float4*)(hres + (size_t)row * DF + hl * 8);
                float4 h1 = *(const float4*)(hres + (size_t)row * DF + hl * 8 + 4);
                acc[0] = fmaf(escale, h0.x, acc[0]);
                acc[1] = fmaf(escale, h0.y, acc[1]);
                acc[2] = fmaf(escale, h0.z, acc[2]);
                acc[3] = fmaf(escale, h0.w, acc[3]);
                acc[4] = fmaf(escale, h1.x, acc[4]);
                acc[5] = fmaf(escale, h1.y, acc[5]);
                acc[6] = fmaf(escale, h1.z, acc[6]);
                acc[7] = fmaf(escale, h1.w, acc[7]);
            }
            #pragma unroll
            for (int cc = 0; cc < 2; ++cc) {
                int c4 = 2 * hl + cc;
                int a = (c4 & 1) * 8 + (c4 & 2);
                __half* p = Xs + r * XS_STRIDE + (c4 >> 2) * 16 + a;
                float* A = acc + cc * 4;
                *(__half2*)p       = __floats2half2_rn(A[0], A[1]);
                *(__half2*)(p + 4) = __floats2half2_rn(A[2], A[3]);
            }
        }
        __syncthreads();

        float acc[8][4];

        // ================= pass 1: X @ W1 =================
        #pragma unroll
        for (int j = 0; j < 8; ++j) {
            acc[j][0] = 0.f; acc[j][1] = 0.f; acc[j][2] = 0.f; acc[j][3] = 0.f;
        }
        #pragma unroll
        for (int s = 0; s < 8; ++s) {
            uint2 av0 = *(const uint2*)(Xs + (wr + fr)     * XS_STRIDE + s * 16 + qd * 4);
            uint2 av1 = *(const uint2*)(Xs + (wr + fr + 8) * XS_STRIDE + s * 16 + qd * 4);
            #pragma unroll
            for (int j = 0; j < 8; ++j) {
                uint2 bv = *(const uint2*)(Ws1 + ((s * 128) + wc + j * 8 + fr) * 16 + qd * 4);
                asm volatile(
                    "mma.sync.aligned.m16n8k16.row.col.f32.f16.f16.f32 "
                    "{%0,%1,%2,%3}, {%4,%5,%6,%7}, {%8,%9}, {%0,%1,%2,%3};"
                    : "+f"(acc[j][0]), "+f"(acc[j][1]), "+f"(acc[j][2]), "+f"(acc[j][3])
                    : "r"(av0.x), "r"(av1.x), "r"(av0.y), "r"(av1.y),
                      "r"(bv.x), "r"(bv.y));
            }
        }
        __syncthreads();
        #pragma unroll
        for (int j = 0; j < 8; ++j) {
            int n = wc + j * 8 + qd * 2;
            *(__half2*)(Xs + (wr + fr)     * XS_STRIDE + n) = __floats2half2_rn(acc[j][0], acc[j][1]);
            *(__half2*)(Xs + (wr + fr + 8) * XS_STRIDE + n) = __floats2half2_rn(acc[j][2], acc[j][3]);
        }
        __syncthreads();

        // ---- LN1 + ReLU: read natural, write interleaved A-layout (in-place) ----
        {
            float4 b4 = ((const float4*)bs1)[lane];
            float4 g4 = ((const float4*)gs1)[lane];
            float4 e4 = ((const float4*)es1)[lane];
            #pragma unroll
            for (int rr = 0; rr < 8; ++rr) {
                int lrow = warp * 8 + rr;
                __half* R = Xs + lrow * XS_STRIDE;
                const __half2* qq2 = (const __half2*)(R + lane * 4);
                float2 f0 = __half22float2(qq2[0]);
                float2 f1 = __half22float2(qq2[1]);
                float a0 = f0.x + b4.x, a1 = f0.y + b4.y, a2 = f1.x + b4.z, a3 = f1.y + b4.w;
                float s = a0 + a1 + a2 + a3;
                float q = a0 * a0 + a1 * a1 + a2 * a2 + a3 * a3;
                #pragma unroll
                for (int off = 16; off > 0; off >>= 1) {
                    s += __shfl_xor_sync(0xFFFFFFFFu, s, off);
                    q += __shfl_xor_sync(0xFFFFFFFFu, q, off);
                }
                float mu   = s * (1.0f / 128.0f);
                float var  = q * (1.0f / 128.0f) - mu * mu;
                float rstd = rsqrtf(var + 1e-5f);
                float o0 = fmaxf(0.f, (a0 - mu) * rstd * g4.x + e4.x);
                float o1 = fmaxf(0.f, (a1 - mu) * rstd * g4.y + e4.y);
                float o2 = fmaxf(0.f, (a2 - mu) * rstd * g4.z + e4.z);
                float o3 = fmaxf(0.f, (a3 - mu) * rstd * g4.w + e4.w);
                int a = (lane & 1) * 8 + (lane & 2);
                __half* p = R + (lane >> 2) * 16 + a;
                *(__half2*)p       = __floats2half2_rn(o0, o1);
                *(__half2*)(p + 4) = __floats2half2_rn(o2, o3);
            }
        }
        __syncthreads();

        // ================= pass 2: Y @ W2 =================
        #pragma unroll
        for (int j = 0; j < 8; ++j) {
            acc[j][0] = 0.f; acc[j][1] = 0.f; acc[j][2] = 0.f; acc[j][3] = 0.f;
        }
        #pragma unroll
        for (int s = 0; s < 8; ++s) {
            uint2 av0 = *(const uint2*)(Xs + (wr + fr)     * XS_STRIDE + s * 16 + qd * 4);
            uint2 av1 = *(const uint2*)(Xs + (wr + fr + 8) * XS_STRIDE + s * 16 + qd * 4);
            #pragma unroll
            for (int j = 0; j < 8; ++j) {
                uint2 bv = *(const uint2*)(Ws2 + ((s * 128) + wc + j * 8 + fr) * 16 + qd * 4);
                asm volatile(
                    "mma.sync.aligned.m16n8k16.row.col.f32.f16.f16.f32 "
                    "{%0,%1,%2,%3}, {%4,%5,%6,%7}, {%8,%9}, {%0,%1,%2,%3};"
                    : "+f"(acc[j][0]), "+f"(acc[j][1]), "+f"(acc[j][2]), "+f"(acc[j][3])
                    : "r"(av0.x), "r"(av1.x), "r"(av0.y), "r"(av1.y),
                      "r"(bv.x), "r"(bv.y));
            }
        }
        __syncthreads();
        #pragma unroll
        for (int j = 0; j < 8; ++j) {
            int n = wc + j * 8 + qd * 2;
            *(__half2*)(Xs + (wr + fr)     * XS_STRIDE + n) = __floats2half2_rn(acc[j][0], acc[j][1]);
            *(__half2*)(Xs + (wr + fr + 8) * XS_STRIDE + n) = __floats2half2_rn(acc[j][2], acc[j][3]);
        }
        __syncthreads();

        // ---- LN2 + ReLU -> gmem (fp32 + fp16 copy) ----
        {
            float4 b4 = ((const float4*)bs2)[lane];
            float4 g4 = ((const float4*)gs2)[lane];
            float4 e4 = ((const float4*)es2)[lane];
            #pragma unroll
            for (int rr = 0; rr < 8; ++rr) {
                int lrow = warp * 8 + rr;
                int grow = rowBlk + lrow;
                const __half2* qq2 = (const __half2*)(Xs + lrow * XS_STRIDE + lane * 4);
                float2 f0 = __half22float2(qq2[0]);
                float2 f1 = __half22float2(qq2[1]);
                float a0 = f0.x + b4.x, a1 = f0.y + b4.y, a2 = f1.x + b4.z, a3 = f1.y + b4.w;
                float s = a0 + a1 + a2 + a3;
                float q = a0 * a0 + a1 * a1 + a2 * a2 + a3 * a3;
                #pragma unroll
                for (int off = 16; off > 0; off >>= 1) {
                    s += __shfl_xor_sync(0xFFFFFFFFu, s, off);
                    q += __shfl_xor_sync(0xFFFFFFFFu, q, off);
                }
                float mu   = s * (1.0f / 128.0f);
                float var  = q * (1.0f / 128.0f) - mu * mu;
                float rstd = rsqrtf(var + 1e-5f);
                float4 o;
                o.x = fmaxf(0.f, (a0 - mu) * rstd * g4.x + e4.x);
                o.y = fmaxf(0.f, (a1 - mu) * rstd * g4.y + e4.y);
                o.z = fmaxf(0.f, (a2 - mu) * rstd * g4.z + e4.z);
                o.w = fmaxf(0.f, (a3 - mu) * rstd * g4.w + e4.w);
                if (grow < nrows) {
                    *(float4*)(out + (size_t)grow * DF + lane * 4) = o;
                    __half2 p2[2];
                    p2[0] = __floats2half2_rn(o.x, o.y);
                    p2[1] = __floats2half2_rn(o.z, o.w);
                    *(float2*)(out16 + (size_t)grow * DF + lane * 4) = *(float2*)p2;
                }
            }
        }
        __syncthreads();
    }
}

// ---------------------------------------------------------------------------
__global__ void pool_kernel(const float* __restrict__ h, const int* __restrict__ gid,
                            float* __restrict__ pool, int N) {
    int c  = threadIdx.x;
    int n0 = blockIdx.x * 128;
    if (n0 >= N) return;
    int curg = __ldg(gid + n0);
    float acc = 0.f;
    #pragma unroll 4
    for (int i = 0; i < 128; ++i) {
        int n = n0 + i;
        if (n >= N) break;
        int g = __ldg(gid + n);
        if (g != curg) {
            atomicAdd(&pool[(size_t)curg * DF + c], acc);
            acc = 0.f;
            curg = g;
        }
        acc += __ldg(h + (size_t)n * DF + c);
    }
    atomicAdd(&pool[(size_t)curg * DF + c], acc);
}

// ---------------------------------------------------------------------------
__global__ void head_kernel(const float* __restrict__ pool, const float* __restrict__ desc,
                            const float* __restrict__ fc1W, const float* __restrict__ fc1b,
                            const float* __restrict__ n1g, const float* __restrict__ n1b,
                            const float* __restrict__ fc2W, const float* __restrict__ fc2b,
                            float* __restrict__ out, int X, int C) {
    int g = blockIdx.x;
    int t = threadIdx.x;
    int warp = t >> 5, lane = t & 31;

    __shared__ float xin[DF + 64];
    __shared__ float ss[4], qq[4];

    xin[t] = pool[(size_t)g * DF + t];
    if (t < X) xin[DF + t] = desc[(size_t)g * X + t];
    __syncthreads();

    int K = DF + X;
    float acc = fc1b[t];
    for (int k = 0; k < K; ++k)
        acc = fmaf(xin[k], __ldg(fc1W + (size_t)k * DF + t), acc);

    float s = acc, q = acc * acc;
    #pragma unroll
    for (int off = 16; off > 0; off >>= 1) {
        s += __shfl_xor_sync(0xFFFFFFFFu, s, off);
        q += __shfl_xor_sync(0xFFFFFFFFu, q, off);
    }
    if (lane == 0) { ss[warp] = s; qq[warp] = q; }
    __syncthreads();
    s = ss[0] + ss[1] + ss[2] + ss[3];
    q = qq[0] + qq[1] + qq[2] + qq[3];
    float mu   = s * (1.0f / 128.0f);
    float var  = q * (1.0f / 128.0f) - mu * mu;
    float rstd = rsqrtf(var + 1e-5f);
    float y = fmaxf(0.f, (acc - mu) * rstd * n1g[t] + n1b[t]);

    for (int c = 0; c < C; ++c) {
        float p = y * __ldg(fc2W + (size_t)t * C + c);
        #pragma unroll
        for (int off = 16; off > 0; off >>= 1)
            p += __shfl_xor_sync(0xFFFFFFFFu, p, off);
        __syncthreads();
        if (lane == 0) ss[warp] = p;
        __syncthreads();
        if (t == 0) out[(size_t)g * C + c] = ss[0] + ss[1] + ss[2] + ss[3] + fc2b[c];
    }
}

// ---------------------------------------------------------------------------
extern "C" void kernel_launch(void* const* d_in, const int* in_sizes, int n_in,
                              void* d_out, int out_size) {
    const float* h    = (const float*)d_in[0];
    const float* desc = (const float*)d_in[1];
    const int*   src  = (const int*)d_in[2];
    const int*   dst  = (const int*)d_in[3];
    const int*   gid  = (const int*)d_in[4];
    const float* W1   = (const float*)d_in[5];
    const float* b1   = (const float*)d_in[6];
    const float* g1   = (const float*)d_in[7];
    const float* be1  = (const float*)d_in[8];
    const float* W2   = (const float*)d_in[9];
    const float* b2   = (const float*)d_in[10];
    const float* eps  = (const float*)d_in[11];
    const float* ng   = (const float*)d_in[12];
    const float* nb   = (const float*)d_in[13];
    const float* fc1W = (const float*)d_in[14];
    const float* fc1b = (const float*)d_in[15];
    const float* n1g  = (const float*)d_in[16];
    const float* n1b  = (const float*)d_in[17];
    const float* fc2W = (const float*)d_in[18];
    const float* fc2b = (const float*)d_in[19];
    float* out = (float*)d_out;

    int N = in_sizes[0] / DF;
    int E = in_sizes[2];
    int L = in_sizes[11];
    int X = in_sizes[14] / DF - DF;
    if (X <= 0) X = 16;
    int G = in_sizes[1] / X;
    int C = in_sizes[18] / DF;
    if (C <= 0) C = 1;
    if (N > NMAX) N = NMAX;
    if (G > GMAX) G = GMAX;
    if (E > EMAX) E = EMAX;

    float *bufC, *pool;
    __half *h16a, *h16b;
    int *degp, *rowptr, *cursor, *csrc, *bsum;
    cudaGetSymbolAddress((void**)&bufC, g_bufC);
    cudaGetSymbolAddress((void**)&h16a, g_h16a);
    cudaGetSymbolAddress((void**)&h16b, g_h16b);
    cudaGetSymbolAddress((void**)&pool, g_pool);
    cudaGetSymbolAddress((void**)&degp, g_deg);
    cudaGetSymbolAddress((void**)&rowptr, g_rowptr);
    cudaGetSymbolAddress((void**)&cursor, g_cursor);
    cudaGetSymbolAddress((void**)&csrc, g_csrc);
    cudaGetSymbolAddress((void**)&bsum, g_bsum);

    const int SMEM_BYTES = (2 * 128 * 128 + 128 * XS_STRIDE) * 2 + 6 * DF * 4; // 105,472
    cudaFuncSetAttribute(layer_fused,
                         cudaFuncAttributeMaxDynamicSharedMemorySize, SMEM_BYTES);

    // --- CSR build + fp16 convert of input h (once per launch) ---
    int nb_scan = (N + 1023) / 1024;
    cudaMemsetAsync(degp, 0, (size_t)N * sizeof(int));
    deg_kernel<<<(E + 255) / 256, 256>>>(dst, degp, E);
    scan1_kernel<<<nb_scan, 1024>>>(degp, rowptr, bsum, N);
    scan2_kernel<<<1, 32>>>(bsum, nb_scan);
    scan3_kernel<<<nb_scan, 1024>>>(rowptr, bsum, cursor, N, E);
    scatter_kernel<<<(E + 255) / 256, 256>>>(src, dst, cursor, csrc, E);
    int nd4 = N * (DF / 4);
    cvt16_kernel<<<(nd4 + 255) / 256, 256>>>(h, h16a, nd4);

    int ntiles = (N + 127) / 128;
    int fgrid = ntiles < 296 ? ntiles : 296;

    __half* hin  = h16a;
    __half* hout = h16b;
    const float* hcur = h;
    for (int l = 0; l < L; ++l) {
        layer_fused<<<fgrid, 512, SMEM_BYTES>>>(
            hin, hcur, rowptr, csrc, eps, l,
            W1 + (size_t)l * DF * DF, b1 + (size_t)l * DF,
            g1 + (size_t)l * DF, be1 + (size_t)l * DF,
            W2 + (size_t)l * DF * DF, b2 + (size_t)l * DF,
            ng + (size_t)l * DF, nb + (size_t)l * DF,
            bufC, hout, N, ntiles);
        hcur = bufC;
        __half* t = hin; hin = hout; hout = t;
    }

    cudaMemsetAsync(pool, 0, (size_t)G * DF * sizeof(float));
    pool_kernel<<<(N + 127) / 128, 128>>>(hcur, gid, pool, N);
    head_kernel<<<G, 128>>>(pool, desc, fc1W, fc1b, n1g, n1b, fc2W, fc2b, out, X, C);
}

// round 13
// speedup vs baseline: 1.2805x; 1.1215x over previous
#include <cuda_runtime.h>
#include <cuda_fp16.h>
#include <cstdint>

#define DF 128
#define NMAX 100000
#define EMAX 1600000
#define GMAX 1024

// persistent scratch (no allocations allowed)
__device__ __half g_h16a[(size_t)NMAX * DF];
__device__ __half g_h16b[(size_t)NMAX * DF];
__device__ float  g_pool[(size_t)GMAX * DF];
__device__ int    g_deg[NMAX];
__device__ int    g_rowptr[NMAX + 1];
__device__ int    g_cursor[NMAX];
__device__ int    g_csrc[EMAX];
__device__ int    g_bsum[1024];

// ---------------------------------------------------------------------------
// CSR build: degree histogram -> exclusive scan -> scatter
__global__ void deg_kernel(const int* __restrict__ dst, int* __restrict__ deg, int E) {
    int i = blockIdx.x * blockDim.x + threadIdx.x;
    if (i < E) atomicAdd(&deg[__ldg(dst + i)], 1);
}

__global__ void scan1_kernel(const int* __restrict__ deg, int* __restrict__ rowptr,
                             int* __restrict__ bsum, int N) {
    __shared__ int sh[1024];
    int tid = threadIdx.x;
    int i = blockIdx.x * 1024 + tid;
    int v = (i < N) ? deg[i] : 0;
    sh[tid] = v;
    __syncthreads();
    #pragma unroll
    for (int off = 1; off < 1024; off <<= 1) {
        int t = (tid >= off) ? sh[tid - off] : 0;
        __syncthreads();
        sh[tid] += t;
        __syncthreads();
    }
    if (i < N) rowptr[i] = sh[tid] - v;
    if (tid == 1023) bsum[blockIdx.x] = sh[1023];
}

__global__ void scan2_kernel(int* __restrict__ bsum, int nb) {
    if (threadIdx.x == 0 && blockIdx.x == 0) {
        int acc = 0;
        for (int i = 0; i < nb; ++i) {
            int v = bsum[i];
            bsum[i] = acc;
            acc += v;
        }
    }
}

// also writes cursor (saves the memcpy launch)
__global__ void scan3_kernel(int* __restrict__ rowptr, const int* __restrict__ bsum,
                             int* __restrict__ cursor, int N, int E) {
    int i = blockIdx.x * 1024 + threadIdx.x;
    if (i < N) {
        int v = rowptr[i] + bsum[blockIdx.x];
        rowptr[i] = v;
        cursor[i] = v;
    }
    if (i == 0) rowptr[N] = E;
}

__global__ void scatter_kernel(const int* __restrict__ src, const int* __restrict__ dst,
                               int* __restrict__ cursor, int* __restrict__ csrc, int E) {
    int i = blockIdx.x * blockDim.x + threadIdx.x;
    if (i < E) {
        int pos = atomicAdd(&cursor[__ldg(dst + i)], 1);
        csrc[pos] = __ldg(src + i);
    }
}

// ---------------------------------------------------------------------------
// fp32 -> fp16 convert (initial h only)
__global__ void cvt16_kernel(const float* __restrict__ src, __half* __restrict__ dst, int n4) {
    int i = blockIdx.x * blockDim.x + threadIdx.x;
    if (i < n4) {
        float4 v = *(const float4*)(src + i * 4);
        __half2 p2[2];
        p2[0] = __floats2half2_rn(v.x, v.y);
        p2[1] = __floats2half2_rn(v.z, v.w);
        *(float2*)(dst + i * 4) = *(float2*)p2;
    }
}

// ---------------------------------------------------------------------------
__device__ __forceinline__ void acc8(float* acc, uint4 p) {
    float2 f0 = __half22float2(*(__half2*)&p.x);
    float2 f1 = __half22float2(*(__half2*)&p.y);
    float2 f2 = __half22float2(*(__half2*)&p.z);
    float2 f3 = __half22float2(*(__half2*)&p.w);
    acc[0] += f0.x; acc[1] += f0.y;
    acc[2] += f1.x; acc[3] += f1.y;
    acc[4] += f2.x; acc[5] += f2.y;
    acc[6] += f3.x; acc[7] += f3.y;
}

// ---------------------------------------------------------------------------
// Fully fused GIN layer, all-fp16 feature state: staging gathers neighbors
// and the (1+eps)*h residual from the fp16 IN buf, then HMMA m16n8k16 MLP
// with fused LN+ReLU twice; epilogue writes ONLY the fp16 OUT buf
// (double-buffered -> no RAW race across tiles).
#define XS_STRIDE 144

__global__ void __launch_bounds__(512, 2)
layer_fused(const __half* __restrict__ hin16,
            const int* __restrict__ rowptr, const int* __restrict__ csrc,
            const float* __restrict__ epsArr, int layer,
            const float* __restrict__ W1, const float* __restrict__ b1,
            const float* __restrict__ g1, const float* __restrict__ be1,
            const float* __restrict__ W2, const float* __restrict__ b2,
            const float* __restrict__ ng, const float* __restrict__ nb,
            __half* __restrict__ out16,
            int nrows, int ntiles) {
    extern __shared__ __align__(16) char smraw[];
    __half* Ws1 = (__half*)smraw;                       // 128*128 halfs = 32KB
    __half* Ws2 = Ws1 + 128 * 128;                      // 32KB
    __half* Xs  = Ws2 + 128 * 128;                      // 128*144 halfs
    float*  prm = (float*)(Xs + 128 * XS_STRIDE);       // 6*128 floats
    float* bs1 = prm, *gs1 = prm + 128, *es1 = prm + 256;
    float* bs2 = prm + 384, *gs2 = prm + 512, *es2 = prm + 640;

    int tid  = threadIdx.x;
    int lane = tid & 31, warp = tid >> 5;

    // Stage W1/W2 as half, interleaved: Ws[(s*128+n)*16 + pos(k&15)]
    for (int idx = tid; idx < 4096; idx += 512) {
        int k  = idx >> 5;
        int n4 = idx & 31;
        int s  = k >> 4, kq = k & 15;
        int pos = (kq & 1) | (((kq >> 3) & 1) << 1) | (((kq >> 1) & 3) << 2);
        size_t go = (size_t)k * DF + n4 * 4;
        float4 wa = *(const float4*)(W1 + go);
        float4 wb = *(const float4*)(W2 + go);
        int base = ((s * 128) + n4 * 4) * 16 + pos;
        Ws1[base]      = __float2half(wa.x);
        Ws1[base + 16] = __float2half(wa.y);
        Ws1[base + 32] = __float2half(wa.z);
        Ws1[base + 48] = __float2half(wa.w);
        Ws2[base]      = __float2half(wb.x);
        Ws2[base + 16] = __float2half(wb.y);
        Ws2[base + 32] = __float2half(wb.z);
        Ws2[base + 48] = __float2half(wb.w);
    }
    if (tid < DF) {
        bs1[tid] = b1[tid]; gs1[tid] = g1[tid]; es1[tid] = be1[tid];
        bs2[tid] = b2[tid]; gs2[tid] = ng[tid]; es2[tid] = nb[tid];
    }

    float escale = 1.0f + epsArr[layer];

    int wr = (warp & 7) * 16;
    int wc = (warp >> 3) * 64;
    int fr = lane >> 2;
    int qd = lane & 3;
    int hw = lane >> 4;        // half-warp id
    int hl = lane & 15;        // lane within half-warp

    __syncthreads();

    for (int tile = blockIdx.x; tile < ntiles; tile += gridDim.x) {
        int rowBlk = tile * 128;

        // ---- stage: GIN aggregate (gather hin16 neighbors) + fp16 residual ----
        for (int rr = 0; rr < 4; ++rr) {
            int r   = warp * 8 + hw * 4 + rr;
            int row = rowBlk + r;
            float acc[8] = {0.f, 0.f, 0.f, 0.f, 0.f, 0.f, 0.f, 0.f};
            if (row < nrows) {
                int beg = __ldg(rowptr + row), end = __ldg(rowptr + row + 1);
                int i = beg;
                for (; i + 4 <= end; i += 4) {
                    int u0 = __ldg(csrc + i),     u1 = __ldg(csrc + i + 1);
                    int u2 = __ldg(csrc + i + 2), u3 = __ldg(csrc + i + 3);
                    uint4 p0 = *(const uint4*)(hin16 + (size_t)u0 * DF + hl * 8);
                    uint4 p1 = *(const uint4*)(hin16 + (size_t)u1 * DF + hl * 8);
                    uint4 p2 = *(const uint4*)(hin16 + (size_t)u2 * DF + hl * 8);
                    uint4 p3 = *(const uint4*)(hin16 + (size_t)u3 * DF + hl * 8);
                    acc8(acc, p0); acc8(acc, p1); acc8(acc, p2); acc8(acc, p3);
                }
                for (; i < end; ++i) {
                    int u = __ldg(csrc + i);
                    uint4 p = *(const uint4*)(hin16 + (size_t)u * DF + hl * 8);
                    acc8(acc, p);
                }
                // residual from own row of the (read-only) IN buffer
                uint4 hp = *(const uint4*)(hin16 + (size_t)row * DF + hl * 8);
                float2 h0 = __half22float2(*(__half2*)&hp.x);
                float2 h1 = __half22float2(*(__half2*)&hp.y);
                float2 h2 = __half22float2(*(__half2*)&hp.z);
                float2 h3 = __half22float2(*(__half2*)&hp.w);
                acc[0] = fmaf(escale, h0.x, acc[0]);
                acc[1] = fmaf(escale, h0.y, acc[1]);
                acc[2] = fmaf(escale, h1.x, acc[2]);
                acc[3] = fmaf(escale, h1.y, acc[3]);
                acc[4] = fmaf(escale, h2.x, acc[4]);
                acc[5] = fmaf(escale, h2.y, acc[5]);
                acc[6] = fmaf(escale, h3.x, acc[6]);
                acc[7] = fmaf(escale, h3.y, acc[7]);
            }
            #pragma unroll
            for (int cc = 0; cc < 2; ++cc) {
                int c4 = 2 * hl + cc;
                int a = (c4 & 1) * 8 + (c4 & 2);
                __half* p = Xs + r * XS_STRIDE + (c4 >> 2) * 16 + a;
                float* A = acc + cc * 4;
                *(__half2*)p       = __floats2half2_rn(A[0], A[1]);
                *(__half2*)(p + 4) = __floats2half2_rn(A[2], A[3]);
            }
        }
        __syncthreads();

        float acc[8][4];

        // ================= pass 1: X @ W1 =================
        #pragma unroll
        for (int j = 0; j < 8; ++j) {
            acc[j][0] = 0.f; acc[j][1] = 0.f; acc[j][2] = 0.f; acc[j][3] = 0.f;
        }
        #pragma unroll
        for (int s = 0; s < 8; ++s) {
            uint2 av0 = *(const uint2*)(Xs + (wr + fr)     * XS_STRIDE + s * 16 + qd * 4);
            uint2 av1 = *(const uint2*)(Xs + (wr + fr + 8) * XS_STRIDE + s * 16 + qd * 4);
            #pragma unroll
            for (int j = 0; j < 8; ++j) {
                uint2 bv = *(const uint2*)(Ws1 + ((s * 128) + wc + j * 8 + fr) * 16 + qd * 4);
                asm volatile(
                    "mma.sync.aligned.m16n8k16.row.col.f32.f16.f16.f32 "
                    "{%0,%1,%2,%3}, {%4,%5,%6,%7}, {%8,%9}, {%0,%1,%2,%3};"
                    : "+f"(acc[j][0]), "+f"(acc[j][1]), "+f"(acc[j][2]), "+f"(acc[j][3])
                    : "r"(av0.x), "r"(av1.x), "r"(av0.y), "r"(av1.y),
                      "r"(bv.x), "r"(bv.y));
            }
        }
        __syncthreads();
        #pragma unroll
        for (int j = 0; j < 8; ++j) {
            int n = wc + j * 8 + qd * 2;
            *(__half2*)(Xs + (wr + fr)     * XS_STRIDE + n) = __floats2half2_rn(acc[j][0], acc[j][1]);
            *(__half2*)(Xs + (wr + fr + 8) * XS_STRIDE + n) = __floats2half2_rn(acc[j][2], acc[j][3]);
        }
        __syncthreads();

        // ---- LN1 + ReLU: read natural, write interleaved A-layout (in-place) ----
        {
            float4 b4 = ((const float4*)bs1)[lane];
            float4 g4 = ((const float4*)gs1)[lane];
            float4 e4 = ((const float4*)es1)[lane];
            #pragma unroll
            for (int rr = 0; rr < 8; ++rr) {
                int lrow = warp * 8 + rr;
                __half* R = Xs + lrow * XS_STRIDE;
                const __half2* qq2 = (const __half2*)(R + lane * 4);
                float2 f0 = __half22float2(qq2[0]);
                float2 f1 = __half22float2(qq2[1]);
                float a0 = f0.x + b4.x, a1 = f0.y + b4.y, a2 = f1.x + b4.z, a3 = f1.y + b4.w;
                float s = a0 + a1 + a2 + a3;
                float q = a0 * a0 + a1 * a1 + a2 * a2 + a3 * a3;
                #pragma unroll
                for (int off = 16; off > 0; off >>= 1) {
                    s += __shfl_xor_sync(0xFFFFFFFFu, s, off);
                    q += __shfl_xor_sync(0xFFFFFFFFu, q, off);
                }
                float mu   = s * (1.0f / 128.0f);
                float var  = q * (1.0f / 128.0f) - mu * mu;
                float rstd = rsqrtf(var + 1e-5f);
                float o0 = fmaxf(0.f, (a0 - mu) * rstd * g4.x + e4.x);
                float o1 = fmaxf(0.f, (a1 - mu) * rstd * g4.y + e4.y);
                float o2 = fmaxf(0.f, (a2 - mu) * rstd * g4.z + e4.z);
                float o3 = fmaxf(0.f, (a3 - mu) * rstd * g4.w + e4.w);
                int a = (lane & 1) * 8 + (lane & 2);
                __half* p = R + (lane >> 2) * 16 + a;
                *(__half2*)p       = __floats2half2_rn(o0, o1);
                *(__half2*)(p + 4) = __floats2half2_rn(o2, o3);
            }
        }
        __syncthreads();

        // ================= pass 2: Y @ W2 =================
        #pragma unroll
        for (int j = 0; j < 8; ++j) {
            acc[j][0] = 0.f; acc[j][1] = 0.f; acc[j][2] = 0.f; acc[j][3] = 0.f;
        }
        #pragma unroll
        for (int s = 0; s < 8; ++s) {
            uint2 av0 = *(const uint2*)(Xs + (wr + fr)     * XS_STRIDE + s * 16 + qd * 4);
            uint2 av1 = *(const uint2*)(Xs + (wr + fr + 8) * XS_STRIDE + s * 16 + qd * 4);
            #pragma unroll
            for (int j = 0; j < 8; ++j) {
                uint2 bv = *(const uint2*)(Ws2 + ((s * 128) + wc + j * 8 + fr) * 16 + qd * 4);
                asm volatile(
                    "mma.sync.aligned.m16n8k16.row.col.f32.f16.f16.f32 "
                    "{%0,%1,%2,%3}, {%4,%5,%6,%7}, {%8,%9}, {%0,%1,%2,%3};"
                    : "+f"(acc[j][0]), "+f"(acc[j][1]), "+f"(acc[j][2]), "+f"(acc[j][3])
                    : "r"(av0.x), "r"(av1.x), "r"(av0.y), "r"(av1.y),
                      "r"(bv.x), "r"(bv.y));
            }
        }
        __syncthreads();
        #pragma unroll
        for (int j = 0; j < 8; ++j) {
            int n = wc + j * 8 + qd * 2;
            *(__half2*)(Xs + (wr + fr)     * XS_STRIDE + n) = __floats2half2_rn(acc[j][0], acc[j][1]);
            *(__half2*)(Xs + (wr + fr + 8) * XS_STRIDE + n) = __floats2half2_rn(acc[j][2], acc[j][3]);
        }
        __syncthreads();

        // ---- LN2 + ReLU -> fp16 gmem only ----
        {
            float4 b4 = ((const float4*)bs2)[lane];
            float4 g4 = ((const float4*)gs2)[lane];
            float4 e4 = ((const float4*)es2)[lane];
            #pragma unroll
            for (int rr = 0; rr < 8; ++rr) {
                int lrow = warp * 8 + rr;
                int grow = rowBlk + lrow;
                const __half2* qq2 = (const __half2*)(Xs + lrow * XS_STRIDE + lane * 4);
                float2 f0 = __half22float2(qq2[0]);
                float2 f1 = __half22float2(qq2[1]);
                float a0 = f0.x + b4.x, a1 = f0.y + b4.y, a2 = f1.x + b4.z, a3 = f1.y + b4.w;
                float s = a0 + a1 + a2 + a3;
                float q = a0 * a0 + a1 * a1 + a2 * a2 + a3 * a3;
                #pragma unroll
                for (int off = 16; off > 0; off >>= 1) {
                    s += __shfl_xor_sync(0xFFFFFFFFu, s, off);
                    q += __shfl_xor_sync(0xFFFFFFFFu, q, off);
                }
                float mu   = s * (1.0f / 128.0f);
                float var  = q * (1.0f / 128.0f) - mu * mu;
                float rstd = rsqrtf(var + 1e-5f);
                float o0 = fmaxf(0.f, (a0 - mu) * rstd * g4.x + e4.x);
                float o1 = fmaxf(0.f, (a1 - mu) * rstd * g4.y + e4.y);
                float o2 = fmaxf(0.f, (a2 - mu) * rstd * g4.z + e4.z);
                float o3 = fmaxf(0.f, (a3 - mu) * rstd * g4.w + e4.w);
                if (grow < nrows) {
                    __half2 p2[2];
                    p2[0] = __floats2half2_rn(o0, o1);
                    p2[1] = __floats2half2_rn(o2, o3);
                    *(float2*)(out16 + (size_t)grow * DF + lane * 4) = *(float2*)p2;
                }
            }
        }
        __syncthreads();
    }
}

// ---------------------------------------------------------------------------
// sum-pool from fp16 features (gid sorted, boundary flush)
__global__ void pool_kernel(const __half* __restrict__ h16, const int* __restrict__ gid,
                            float* __restrict__ pool, int N) {
    int c  = threadIdx.x;
    int n0 = blockIdx.x * 128;
    if (n0 >= N) return;
    int curg = __ldg(gid + n0);
    float acc = 0.f;
    #pragma unroll 4
    for (int i = 0; i < 128; ++i) {
        int n = n0 + i;
        if (n >= N) break;
        int g = __ldg(gid + n);
        if (g != curg) {
            atomicAdd(&pool[(size_t)curg * DF + c], acc);
            acc = 0.f;
            curg = g;
        }
        acc += __half2float(h16[(size_t)n * DF + c]);
    }
    atomicAdd(&pool[(size_t)curg * DF + c], acc);
}

// ---------------------------------------------------------------------------
__global__ void head_kernel(const float* __restrict__ pool, const float* __restrict__ desc,
                            const float* __restrict__ fc1W, const float* __restrict__ fc1b,
                            const float* __restrict__ n1g, const float* __restrict__ n1b,
                            const float* __restrict__ fc2W, const float* __restrict__ fc2b,
                            float* __restrict__ out, int X, int C) {
    int g = blockIdx.x;
    int t = threadIdx.x;
    int warp = t >> 5, lane = t & 31;

    __shared__ float xin[DF + 64];
    __shared__ float ss[4], qq[4];

    xin[t] = pool[(size_t)g * DF + t];
    if (t < X) xin[DF + t] = desc[(size_t)g * X + t];
    __syncthreads();

    int K = DF + X;
    float acc = fc1b[t];
    for (int k = 0; k < K; ++k)
        acc = fmaf(xin[k], __ldg(fc1W + (size_t)k * DF + t), acc);

    float s = acc, q = acc * acc;
    #pragma unroll
    for (int off = 16; off > 0; off >>= 1) {
        s += __shfl_xor_sync(0xFFFFFFFFu, s, off);
        q += __shfl_xor_sync(0xFFFFFFFFu, q, off);
    }
    if (lane == 0) { ss[warp] = s; qq[warp] = q; }
    __syncthreads();
    s = ss[0] + ss[1] + ss[2] + ss[3];
    q = qq[0] + qq[1] + qq[2] + qq[3];
    float mu   = s * (1.0f / 128.0f);
    float var  = q * (1.0f / 128.0f) - mu * mu;
    float rstd = rsqrtf(var + 1e-5f);
    float y = fmaxf(0.f, (acc - mu) * rstd * n1g[t] + n1b[t]);

    for (int c = 0; c < C; ++c) {
        float p = y * __ldg(fc2W + (size_t)t * C + c);
        #pragma unroll
        for (int off = 16; off > 0; off >>= 1)
            p += __shfl_xor_sync(0xFFFFFFFFu, p, off);
        __syncthreads();
        if (lane == 0) ss[warp] = p;
        __syncthreads();
        if (t == 0) out[(size_t)g * C + c] = ss[0] + ss[1] + ss[2] + ss[3] + fc2b[c];
    }
}

// ---------------------------------------------------------------------------
extern "C" void kernel_launch(void* const* d_in, const int* in_sizes, int n_in,
                              void* d_out, int out_size) {
    const float* h    = (const float*)d_in[0];
    const float* desc = (const float*)d_in[1];
    const int*   src  = (const int*)d_in[2];
    const int*   dst  = (const int*)d_in[3];
    const int*   gid  = (const int*)d_in[4];
    const float* W1   = (const float*)d_in[5];
    const float* b1   = (const float*)d_in[6];
    const float* g1   = (const float*)d_in[7];
    const float* be1  = (const float*)d_in[8];
    const float* W2   = (const float*)d_in[9];
    const float* b2   = (const float*)d_in[10];
    const float* eps  = (const float*)d_in[11];
    const float* ng   = (const float*)d_in[12];
    const float* nb   = (const float*)d_in[13];
    const float* fc1W = (const float*)d_in[14];
    const float* fc1b = (const float*)d_in[15];
    const float* n1g  = (const float*)d_in[16];
    const float* n1b  = (const float*)d_in[17];
    const float* fc2W = (const float*)d_in[18];
    const float* fc2b = (const float*)d_in[19];
    float* out = (float*)d_out;

    int N = in_sizes[0] / DF;
    int E = in_sizes[2];
    int L = in_sizes[11];
    int X = in_sizes[14] / DF - DF;
    if (X <= 0) X = 16;
    int G = in_sizes[1] / X;
    int C = in_sizes[18] / DF;
    if (C <= 0) C = 1;
    if (N > NMAX) N = NMAX;
    if (G > GMAX) G = GMAX;
    if (E > EMAX) E = EMAX;

    float *pool;
    __half *h16a, *h16b;
    int *degp, *rowptr, *cursor, *csrc, *bsum;
    cudaGetSymbolAddress((void**)&h16a, g_h16a);
    cudaGetSymbolAddress((void**)&h16b, g_h16b);
    cudaGetSymbolAddress((void**)&pool, g_pool);
    cudaGetSymbolAddress((void**)&degp, g_deg);
    cudaGetSymbolAddress((void**)&rowptr, g_rowptr);
    cudaGetSymbolAddress((void**)&cursor, g_cursor);
    cudaGetSymbolAddress((void**)&csrc, g_csrc);
    cudaGetSymbolAddress((void**)&bsum, g_bsum);

    const int SMEM_BYTES = (2 * 128 * 128 + 128 * XS_STRIDE) * 2 + 6 * DF * 4; // 105,472
    cudaFuncSetAttribute(layer_fused,
                         cudaFuncAttributeMaxDynamicSharedMemorySize, SMEM_BYTES);

    // --- CSR build + fp16 convert of input h (once per launch) ---
    int nb_scan = (N + 1023) / 1024;
    cudaMemsetAsync(degp, 0, (size_t)N * sizeof(int));
    deg_kernel<<<(E + 255) / 256, 256>>>(dst, degp, E);
    scan1_kernel<<<nb_scan, 1024>>>(degp, rowptr, bsum, N);
    scan2_kernel<<<1, 32>>>(bsum, nb_scan);
    scan3_kernel<<<nb_scan, 1024>>>(rowptr, bsum, cursor, N, E);
    scatter_kernel<<<(E + 255) / 256, 256>>>(src, dst, cursor, csrc, E);
    int nd4 = N * (DF / 4);
    cvt16_kernel<<<(nd4 + 255) / 256, 256>>>(h, h16a, nd4);

    int ntiles = (N + 127) / 128;
    int fgrid = ntiles < 296 ? ntiles : 296;

    __half* hin  = h16a;
    __half* hout = h16b;
    for (int l = 0; l < L; ++l) {
        layer_fused<<<fgrid, 512, SMEM_BYTES>>>(
            hin, rowptr, csrc, eps, l,
            W1 + (size_t)l * DF * DF, b1 + (size_t)l * DF,
            g1 + (size_t)l * DF, be1 + (size_t)l * DF,
            W2 + (size_t)l * DF * DF, b2 + (size_t)l * DF,
            ng + (size_t)l * DF, nb + (size_t)l * DF,
            hout, N, ntiles);
        __half* t = hin; hin = hout; hout = t;
    }

    cudaMemsetAsync(pool, 0, (size_t)G * DF * sizeof(float));
    pool_kernel<<<(N + 127) / 128, 128>>>(hin, gid, pool, N);
    head_kernel<<<G, 128>>>(pool, desc, fc1W, fc1b, n1g, n1b, fc2W, fc2b, out, X, C);
}

// round 14
// speedup vs baseline: 1.3467x; 1.0517x over previous
#include <cuda_runtime.h>
#include <cuda_fp16.h>
#include <cstdint>

#define DF 128
#define NMAX 100000
#define EMAX 1600000
#define GMAX 1024
#define XS_STRIDE 144

// persistent scratch (no allocations allowed)
__device__ __half g_h16a[(size_t)NMAX * DF];
__device__ __half g_h16b[(size_t)NMAX * DF];
__device__ float  g_pool[(size_t)GMAX * DF];
__device__ int    g_deg[NMAX];
__device__ int    g_rowptr[NMAX + 1];
__device__ int    g_cursor[NMAX];
__device__ int    g_csrc[EMAX];
__device__ int    g_bsum[1024];

#define BAR_SYNC(id, cnt)   asm volatile("bar.sync %0, %1;"   :: "r"(id), "r"(cnt) : "memory")
#define BAR_ARRIVE(id, cnt) asm volatile("bar.arrive %0, %1;" :: "r"(id), "r"(cnt) : "memory")

// ---------------------------------------------------------------------------
// CSR build: degree histogram -> exclusive scan -> scatter
__global__ void deg_kernel(const int* __restrict__ dst, int* __restrict__ deg, int E) {
    int i = blockIdx.x * blockDim.x + threadIdx.x;
    if (i < E) atomicAdd(&deg[__ldg(dst + i)], 1);
}

__global__ void scan1_kernel(const int* __restrict__ deg, int* __restrict__ rowptr,
                             int* __restrict__ bsum, int N) {
    __shared__ int sh[1024];
    int tid = threadIdx.x;
    int i = blockIdx.x * 1024 + tid;
    int v = (i < N) ? deg[i] : 0;
    sh[tid] = v;
    __syncthreads();
    #pragma unroll
    for (int off = 1; off < 1024; off <<= 1) {
        int t = (tid >= off) ? sh[tid - off] : 0;
        __syncthreads();
        sh[tid] += t;
        __syncthreads();
    }
    if (i < N) rowptr[i] = sh[tid] - v;
    if (tid == 1023) bsum[blockIdx.x] = sh[1023];
}

__global__ void scan2_kernel(int* __restrict__ bsum, int nb) {
    if (threadIdx.x == 0 && blockIdx.x == 0) {
        int acc = 0;
        for (int i = 0; i < nb; ++i) {
            int v = bsum[i];
            bsum[i] = acc;
            acc += v;
        }
    }
}

__global__ void scan3_kernel(int* __restrict__ rowptr, const int* __restrict__ bsum,
                             int* __restrict__ cursor, int N, int E) {
    int i = blockIdx.x * 1024 + threadIdx.x;
    if (i < N) {
        int v = rowptr[i] + bsum[blockIdx.x];
        rowptr[i] = v;
        cursor[i] = v;
    }
    if (i == 0) rowptr[N] = E;
}

__global__ void scatter_kernel(const int* __restrict__ src, const int* __restrict__ dst,
                               int* __restrict__ cursor, int* __restrict__ csrc, int E) {
    int i = blockIdx.x * blockDim.x + threadIdx.x;
    if (i < E) {
        int pos = atomicAdd(&cursor[__ldg(dst + i)], 1);
        csrc[pos] = __ldg(src + i);
    }
}

// ---------------------------------------------------------------------------
__global__ void cvt16_kernel(const float* __restrict__ src, __half* __restrict__ dst, int n4) {
    int i = blockIdx.x * blockDim.x + threadIdx.x;
    if (i < n4) {
        float4 v = *(const float4*)(src + i * 4);
        __half2 p2[2];
        p2[0] = __floats2half2_rn(v.x, v.y);
        p2[1] = __floats2half2_rn(v.z, v.w);
        *(float2*)(dst + i * 4) = *(float2*)p2;
    }
}

// ---------------------------------------------------------------------------
__device__ __forceinline__ void acc8(float* acc, uint4 p) {
    float2 f0 = __half22float2(*(__half2*)&p.x);
    float2 f1 = __half22float2(*(__half2*)&p.y);
    float2 f2 = __half22float2(*(__half2*)&p.z);
    float2 f3 = __half22float2(*(__half2*)&p.w);
    acc[0] += f0.x; acc[1] += f0.y;
    acc[2] += f1.x; acc[3] += f1.y;
    acc[4] += f2.x; acc[5] += f2.y;
    acc[6] += f3.x; acc[7] += f3.y;
}

// ---------------------------------------------------------------------------
// Warp-specialized fused GIN layer: 1024 threads.
// Warps 0-15 (producers): gather GIN aggregation + residual into Xs[buf].
// Warps 16-31 (consumers): HMMA m16n8k16 MLP + LN/ReLU x2, write fp16 out.
// Double-buffered Xs; named barriers: full[buf]=2+buf, empty[buf]=4+buf
// (count 1024: 512 arrive + 512 sync), consumer-internal barrier 6 (count 512).
__global__ void __launch_bounds__(1024, 1)
layer_fused(const __half* __restrict__ hin16,
            const int* __restrict__ rowptr, const int* __restrict__ csrc,
            const float* __restrict__ epsArr, int layer,
            const float* __restrict__ W1, const float* __restrict__ b1,
            const float* __restrict__ g1, const float* __restrict__ be1,
            const float* __restrict__ W2, const float* __restrict__ b2,
            const float* __restrict__ ng, const float* __restrict__ nb,
            __half* __restrict__ out16,
            int nrows, int ntiles) {
    extern __shared__ __align__(16) char smraw[];
    __half* Ws1 = (__half*)smraw;                        // 16384 halfs
    __half* Ws2 = Ws1 + 128 * 128;                       // 16384 halfs
    __half* Xs0 = Ws2 + 128 * 128;                       // 128*144 halfs
    __half* Xs1 = Xs0 + 128 * XS_STRIDE;                 // 128*144 halfs
    float*  prm = (float*)(Xs1 + 128 * XS_STRIDE);       // 6*128 floats
    float* bs1 = prm, *gs1 = prm + 128, *es1 = prm + 256;
    float* bs2 = prm + 384, *gs2 = prm + 512, *es2 = prm + 640;

    int tid  = threadIdx.x;
    int lane = tid & 31, warp = tid >> 5;

    // Stage W1/W2 as half, interleaved: Ws[(s*128+n)*16 + pos(k&15)]
    for (int idx = tid; idx < 4096; idx += 1024) {
        int k  = idx >> 5;
        int n4 = idx & 31;
        int s  = k >> 4, kq = k & 15;
        int pos = (kq & 1) | (((kq >> 3) & 1) << 1) | (((kq >> 1) & 3) << 2);
        size_t go = (size_t)k * DF + n4 * 4;
        float4 wa = *(const float4*)(W1 + go);
        float4 wb = *(const float4*)(W2 + go);
        int base = ((s * 128) + n4 * 4) * 16 + pos;
        Ws1[base]      = __float2half(wa.x);
        Ws1[base + 16] = __float2half(wa.y);
        Ws1[base + 32] = __float2half(wa.z);
        Ws1[base + 48] = __float2half(wa.w);
        Ws2[base]      = __float2half(wb.x);
        Ws2[base + 16] = __float2half(wb.y);
        Ws2[base + 32] = __float2half(wb.z);
        Ws2[base + 48] = __float2half(wb.w);
    }
    if (tid < DF) {
        bs1[tid] = b1[tid]; gs1[tid] = g1[tid]; es1[tid] = be1[tid];
        bs2[tid] = b2[tid]; gs2[tid] = ng[tid]; es2[tid] = nb[tid];
    }
    __syncthreads();

    float escale = 1.0f + epsArr[layer];

    if (warp < 16) {
        // ======================= PRODUCER =======================
        int pw = warp;
        int hw = lane >> 4;
        int hl = lane & 15;
        int lt = 0;
        for (int tile = blockIdx.x; tile < ntiles; tile += gridDim.x, ++lt) {
            int buf = lt & 1;
            if (lt >= 2) BAR_SYNC(4 + buf, 1024);      // wait empty[buf]
            __half* Xs = buf ? Xs1 : Xs0;
            int rowBlk = tile * 128;
            for (int rr = 0; rr < 4; ++rr) {
                int r   = pw * 8 + hw * 4 + rr;
                int row = rowBlk + r;
                float acc[8] = {0.f, 0.f, 0.f, 0.f, 0.f, 0.f, 0.f, 0.f};
                if (row < nrows) {
                    int beg = __ldg(rowptr + row), end = __ldg(rowptr + row + 1);
                    int i = beg;
                    for (; i + 4 <= end; i += 4) {
                        int u0 = __ldg(csrc + i),     u1 = __ldg(csrc + i + 1);
                        int u2 = __ldg(csrc + i + 2), u3 = __ldg(csrc + i + 3);
                        uint4 p0 = *(const uint4*)(hin16 + (size_t)u0 * DF + hl * 8);
                        uint4 p1 = *(const uint4*)(hin16 + (size_t)u1 * DF + hl * 8);
                        uint4 p2 = *(const uint4*)(hin16 + (size_t)u2 * DF + hl * 8);
                        uint4 p3 = *(const uint4*)(hin16 + (size_t)u3 * DF + hl * 8);
                        acc8(acc, p0); acc8(acc, p1); acc8(acc, p2); acc8(acc, p3);
                    }
                    for (; i < end; ++i) {
                        int u = __ldg(csrc + i);
                        uint4 p = *(const uint4*)(hin16 + (size_t)u * DF + hl * 8);
                        acc8(acc, p);
                    }
                    uint4 hp = *(const uint4*)(hin16 + (size_t)row * DF + hl * 8);
                    float2 h0 = __half22float2(*(__half2*)&hp.x);
                    float2 h1 = __half22float2(*(__half2*)&hp.y);
                    float2 h2 = __half22float2(*(__half2*)&hp.z);
                    float2 h3 = __half22float2(*(__half2*)&hp.w);
                    acc[0] = fmaf(escale, h0.x, acc[0]);
                    acc[1] = fmaf(escale, h0.y, acc[1]);
                    acc[2] = fmaf(escale, h1.x, acc[2]);
                    acc[3] = fmaf(escale, h1.y, acc[3]);
                    acc[4] = fmaf(escale, h2.x, acc[4]);
                    acc[5] = fmaf(escale, h2.y, acc[5]);
                    acc[6] = fmaf(escale, h3.x, acc[6]);
                    acc[7] = fmaf(escale, h3.y, acc[7]);
                }
                #pragma unroll
                for (int cc = 0; cc < 2; ++cc) {
                    int c4 = 2 * hl + cc;
                    int a = (c4 & 1) * 8 + (c4 & 2);
                    __half* p = Xs + r * XS_STRIDE + (c4 >> 2) * 16 + a;
                    float* A = acc + cc * 4;
                    *(__half2*)p       = __floats2half2_rn(A[0], A[1]);
                    *(__half2*)(p + 4) = __floats2half2_rn(A[2], A[3]);
                }
            }
            BAR_ARRIVE(2 + buf, 1024);                 // signal full[buf]
        }
    } else {
        // ======================= CONSUMER =======================
        int cw = warp - 16;
        int wr = (cw & 7) * 16;
        int wc = (cw >> 3) * 64;
        int fr = lane >> 2;
        int qd = lane & 3;
        int lt = 0;
        for (int tile = blockIdx.x; tile < ntiles; tile += gridDim.x, ++lt) {
            int buf = lt & 1;
            BAR_SYNC(2 + buf, 1024);                   // wait full[buf]
            __half* Xs = buf ? Xs1 : Xs0;
            int rowBlk = tile * 128;

            float acc[8][4];

            // ---- pass 1: X @ W1 ----
            #pragma unroll
            for (int j = 0; j < 8; ++j) {
                acc[j][0] = 0.f; acc[j][1] = 0.f; acc[j][2] = 0.f; acc[j][3] = 0.f;
            }
            #pragma unroll
            for (int s = 0; s < 8; ++s) {
                uint2 av0 = *(const uint2*)(Xs + (wr + fr)     * XS_STRIDE + s * 16 + qd * 4);
                uint2 av1 = *(const uint2*)(Xs + (wr + fr + 8) * XS_STRIDE + s * 16 + qd * 4);
                #pragma unroll
                for (int j = 0; j < 8; ++j) {
                    uint2 bv = *(const uint2*)(Ws1 + ((s * 128) + wc + j * 8 + fr) * 16 + qd * 4);
                    asm volatile(
                        "mma.sync.aligned.m16n8k16.row.col.f32.f16.f16.f32 "
                        "{%0,%1,%2,%3}, {%4,%5,%6,%7}, {%8,%9}, {%0,%1,%2,%3};"
                        : "+f"(acc[j][0]), "+f"(acc[j][1]), "+f"(acc[j][2]), "+f"(acc[j][3])
                        : "r"(av0.x), "r"(av1.x), "r"(av0.y), "r"(av1.y),
                          "r"(bv.x), "r"(bv.y));
                }
            }
            BAR_SYNC(6, 512);
            #pragma unroll
            for (int j = 0; j < 8; ++j) {
                int n = wc + j * 8 + qd * 2;
                *(__half2*)(Xs + (wr + fr)     * XS_STRIDE + n) = __floats2half2_rn(acc[j][0], acc[j][1]);
                *(__half2*)(Xs + (wr + fr + 8) * XS_STRIDE + n) = __floats2half2_rn(acc[j][2], acc[j][3]);
            }
            BAR_SYNC(6, 512);

            // ---- LN1 + ReLU (in-place re-permute) ----
            {
                float4 b4 = ((const float4*)bs1)[lane];
                float4 g4 = ((const float4*)gs1)[lane];
                float4 e4 = ((const float4*)es1)[lane];
                #pragma unroll
                for (int rr = 0; rr < 8; ++rr) {
                    int lrow = cw * 8 + rr;
                    __half* R = Xs + lrow * XS_STRIDE;
                    const __half2* qq2 = (const __half2*)(R + lane * 4);
                    float2 f0 = __half22float2(qq2[0]);
                    float2 f1 = __half22float2(qq2[1]);
                    float a0 = f0.x + b4.x, a1 = f0.y + b4.y, a2 = f1.x + b4.z, a3 = f1.y + b4.w;
                    float s = a0 + a1 + a2 + a3;
                    float q = a0 * a0 + a1 * a1 + a2 * a2 + a3 * a3;
                    #pragma unroll
                    for (int off = 16; off > 0; off >>= 1) {
                        s += __shfl_xor_sync(0xFFFFFFFFu, s, off);
                        q += __shfl_xor_sync(0xFFFFFFFFu, q, off);
                    }
                    float mu   = s * (1.0f / 128.0f);
                    float var  = q * (1.0f / 128.0f) - mu * mu;
                    float rstd = rsqrtf(var + 1e-5f);
                    float o0 = fmaxf(0.f, (a0 - mu) * rstd * g4.x + e4.x);
                    float o1 = fmaxf(0.f, (a1 - mu) * rstd * g4.y + e4.y);
                    float o2 = fmaxf(0.f, (a2 - mu) * rstd * g4.z + e4.z);
                    float o3 = fmaxf(0.f, (a3 - mu) * rstd * g4.w + e4.w);
                    int a = (lane & 1) * 8 + (lane & 2);
                    __half* p = R + (lane >> 2) * 16 + a;
                    *(__half2*)p       = __floats2half2_rn(o0, o1);
                    *(__half2*)(p + 4) = __floats2half2_rn(o2, o3);
                }
            }
            BAR_SYNC(6, 512);

            // ---- pass 2: Y @ W2 ----
            #pragma unroll
            for (int j = 0; j < 8; ++j) {
                acc[j][0] = 0.f; acc[j][1] = 0.f; acc[j][2] = 0.f; acc[j][3] = 0.f;
            }
            #pragma unroll
            for (int s = 0; s < 8; ++s) {
                uint2 av0 = *(const uint2*)(Xs + (wr + fr)     * XS_STRIDE + s * 16 + qd * 4);
                uint2 av1 = *(const uint2*)(Xs + (wr + fr + 8) * XS_STRIDE + s * 16 + qd * 4);
                #pragma unroll
                for (int j = 0; j < 8; ++j) {
                    uint2 bv = *(const uint2*)(Ws2 + ((s * 128) + wc + j * 8 + fr) * 16 + qd * 4);
                    asm volatile(
                        "mma.sync.aligned.m16n8k16.row.col.f32.f16.f16.f32 "
                        "{%0,%1,%2,%3}, {%4,%5,%6,%7}, {%8,%9}, {%0,%1,%2,%3};"
                        : "+f"(acc[j][0]), "+f"(acc[j][1]), "+f"(acc[j][2]), "+f"(acc[j][3])
                        : "r"(av0.x), "r"(av1.x), "r"(av0.y), "r"(av1.y),
                          "r"(bv.x), "r"(bv.y));
                }
            }
            BAR_SYNC(6, 512);
            #pragma unroll
            for (int j = 0; j < 8; ++j) {
                int n = wc + j * 8 + qd * 2;
                *(__half2*)(Xs + (wr + fr)     * XS_STRIDE + n) = __floats2half2_rn(acc[j][0], acc[j][1]);
                *(__half2*)(Xs + (wr + fr + 8) * XS_STRIDE + n) = __floats2half2_rn(acc[j][2], acc[j][3]);
            }
            BAR_SYNC(6, 512);

            // ---- LN2 + ReLU -> fp16 gmem ----
            {
                float4 b4 = ((const float4*)bs2)[lane];
                float4 g4 = ((const float4*)gs2)[lane];
                float4 e4 = ((const float4*)es2)[lane];
                #pragma unroll
                for (int rr = 0; rr < 8; ++rr) {
                    int lrow = cw * 8 + rr;
                    int grow = rowBlk + lrow;
                    const __half2* qq2 = (const __half2*)(Xs + lrow * XS_STRIDE + lane * 4);
                    float2 f0 = __half22float2(qq2[0]);
                    float2 f1 = __half22float2(qq2[1]);
                    float a0 = f0.x + b4.x, a1 = f0.y + b4.y, a2 = f1.x + b4.z, a3 = f1.y + b4.w;
                    float s = a0 + a1 + a2 + a3;
                    float q = a0 * a0 + a1 * a1 + a2 * a2 + a3 * a3;
                    #pragma unroll
                    for (int off = 16; off > 0; off >>= 1) {
                        s += __shfl_xor_sync(0xFFFFFFFFu, s, off);
                        q += __shfl_xor_sync(0xFFFFFFFFu, q, off);
                    }
                    float mu   = s * (1.0f / 128.0f);
                    float var  = q * (1.0f / 128.0f) - mu * mu;
                    float rstd = rsqrtf(var + 1e-5f);
                    float o0 = fmaxf(0.f, (a0 - mu) * rstd * g4.x + e4.x);
                    float o1 = fmaxf(0.f, (a1 - mu) * rstd * g4.y + e4.y);
                    float o2 = fmaxf(0.f, (a2 - mu) * rstd * g4.z + e4.z);
                    float o3 = fmaxf(0.f, (a3 - mu) * rstd * g4.w + e4.w);
                    if (grow < nrows) {
                        __half2 p2[2];
                        p2[0] = __floats2half2_rn(o0, o1);
                        p2[1] = __floats2half2_rn(o2, o3);
                        *(float2*)(out16 + (size_t)grow * DF + lane * 4) = *(float2*)p2;
                    }
                }
            }
            BAR_ARRIVE(4 + buf, 1024);                 // signal empty[buf]
        }
    }
}

// ---------------------------------------------------------------------------
__global__ void pool_kernel(const __half* __restrict__ h16, const int* __restrict__ gid,
                            float* __restrict__ pool, int N) {
    int c  = threadIdx.x;
    int n0 = blockIdx.x * 128;
    if (n0 >= N) return;
    int curg = __ldg(gid + n0);
    float acc = 0.f;
    #pragma unroll 4
    for (int i = 0; i < 128; ++i) {
        int n = n0 + i;
        if (n >= N) break;
        int g = __ldg(gid + n);
        if (g != curg) {
            atomicAdd(&pool[(size_t)curg * DF + c], acc);
            acc = 0.f;
            curg = g;
        }
        acc += __half2float(h16[(size_t)n * DF + c]);
    }
    atomicAdd(&pool[(size_t)curg * DF + c], acc);
}

// ---------------------------------------------------------------------------
__global__ void head_kernel(const float* __restrict__ pool, const float* __restrict__ desc,
                            const float* __restrict__ fc1W, const float* __restrict__ fc1b,
                            const float* __restrict__ n1g, const float* __restrict__ n1b,
                            const float* __restrict__ fc2W, const float* __restrict__ fc2b,
                            float* __restrict__ out, int X, int C) {
    int g = blockIdx.x;
    int t = threadIdx.x;
    int warp = t >> 5, lane = t & 31;

    __shared__ float xin[DF + 64];
    __shared__ float ss[4], qq[4];

    xin[t] = pool[(size_t)g * DF + t];
    if (t < X) xin[DF + t] = desc[(size_t)g * X + t];
    __syncthreads();

    int K = DF + X;
    float acc = fc1b[t];
    for (int k = 0; k < K; ++k)
        acc = fmaf(xin[k], __ldg(fc1W + (size_t)k * DF + t), acc);

    float s = acc, q = acc * acc;
    #pragma unroll
    for (int off = 16; off > 0; off >>= 1) {
        s += __shfl_xor_sync(0xFFFFFFFFu, s, off);
        q += __shfl_xor_sync(0xFFFFFFFFu, q, off);
    }
    if (lane == 0) { ss[warp] = s; qq[warp] = q; }
    __syncthreads();
    s = ss[0] + ss[1] + ss[2] + ss[3];
    q = qq[0] + qq[1] + qq[2] + qq[3];
    float mu   = s * (1.0f / 128.0f);
    float var  = q * (1.0f / 128.0f) - mu * mu;
    float rstd = rsqrtf(var + 1e-5f);
    float y = fmaxf(0.f, (acc - mu) * rstd * n1g[t] + n1b[t]);

    for (int c = 0; c < C; ++c) {
        float p = y * __ldg(fc2W + (size_t)t * C + c);
        #pragma unroll
        for (int off = 16; off > 0; off >>= 1)
            p += __shfl_xor_sync(0xFFFFFFFFu, p, off);
        __syncthreads();
        if (lane == 0) ss[warp] = p;
        __syncthreads();
        if (t == 0) out[(size_t)g * C + c] = ss[0] + ss[1] + ss[2] + ss[3] + fc2b[c];
    }
}

// ---------------------------------------------------------------------------
extern "C" void kernel_launch(void* const* d_in, const int* in_sizes, int n_in,
                              void* d_out, int out_size) {
    const float* h    = (const float*)d_in[0];
    const float* desc = (const float*)d_in[1];
    const int*   src  = (const int*)d_in[2];
    const int*   dst  = (const int*)d_in[3];
    const int*   gid  = (const int*)d_in[4];
    const float* W1   = (const float*)d_in[5];
    const float* b1   = (const float*)d_in[6];
    const float* g1   = (const float*)d_in[7];
    const float* be1  = (const float*)d_in[8];
    const float* W2   = (const float*)d_in[9];
    const float* b2   = (const float*)d_in[10];
    const float* eps  = (const float*)d_in[11];
    const float* ng   = (const float*)d_in[12];
    const float* nb   = (const float*)d_in[13];
    const float* fc1W = (const float*)d_in[14];
    const float* fc1b = (const float*)d_in[15];
    const float* n1g  = (const float*)d_in[16];
    const float* n1b  = (const float*)d_in[17];
    const float* fc2W = (const float*)d_in[18];
    const float* fc2b = (const float*)d_in[19];
    float* out = (float*)d_out;

    int N = in_sizes[0] / DF;
    int E = in_sizes[2];
    int L = in_sizes[11];
    int X = in_sizes[14] / DF - DF;
    if (X <= 0) X = 16;
    int G = in_sizes[1] / X;
    int C = in_sizes[18] / DF;
    if (C <= 0) C = 1;
    if (N > NMAX) N = NMAX;
    if (G > GMAX) G = GMAX;
    if (E > EMAX) E = EMAX;

    float *pool;
    __half *h16a, *h16b;
    int *degp, *rowptr, *cursor, *csrc, *bsum;
    cudaGetSymbolAddress((void**)&h16a, g_h16a);
    cudaGetSymbolAddress((void**)&h16b, g_h16b);
    cudaGetSymbolAddress((void**)&pool, g_pool);
    cudaGetSymbolAddress((void**)&degp, g_deg);
    cudaGetSymbolAddress((void**)&rowptr, g_rowptr);
    cudaGetSymbolAddress((void**)&cursor, g_cursor);
    cudaGetSymbolAddress((void**)&csrc, g_csrc);
    cudaGetSymbolAddress((void**)&bsum, g_bsum);

    const int SMEM_BYTES = (2 * 128 * 128 + 2 * 128 * XS_STRIDE) * 2 + 6 * DF * 4; // 142,336
    cudaFuncSetAttribute(layer_fused,
                         cudaFuncAttributeMaxDynamicSharedMemorySize, SMEM_BYTES);

    // --- CSR build + fp16 convert of input h (once per launch) ---
    int nb_scan = (N + 1023) / 1024;
    cudaMemsetAsync(degp, 0, (size_t)N * sizeof(int));
    deg_kernel<<<(E + 255) / 256, 256>>>(dst, degp, E);
    scan1_kernel<<<nb_scan, 1024>>>(degp, rowptr, bsum, N);
    scan2_kernel<<<1, 32>>>(bsum, nb_scan);
    scan3_kernel<<<nb_scan, 1024>>>(rowptr, bsum, cursor, N, E);
    scatter_kernel<<<(E + 255) / 256, 256>>>(src, dst, cursor, csrc, E);
    int nd4 = N * (DF / 4);
    cvt16_kernel<<<(nd4 + 255) / 256, 256>>>(h, h16a, nd4);

    int ntiles = (N + 127) / 128;
    int fgrid = ntiles < 148 ? ntiles : 148;

    __half* hin  = h16a;
    __half* hout = h16b;
    for (int l = 0; l < L; ++l) {
        layer_fused<<<fgrid, 1024, SMEM_BYTES>>>(
            hin, rowptr, csrc, eps, l,
            W1 + (size_t)l * DF * DF, b1 + (size_t)l * DF,
            g1 + (size_t)l * DF, be1 + (size_t)l * DF,
            W2 + (size_t)l * DF * DF, b2 + (size_t)l * DF,
            ng + (size_t)l * DF, nb + (size_t)l * DF,
            hout, N, ntiles);
        __half* t = hin; hin = hout; hout = t;
    }

    cudaMemsetAsync(pool, 0, (size_t)G * DF * sizeof(float));
    pool_kernel<<<(N + 127) / 128, 128>>>(hin, gid, pool, N);
    head_kernel<<<G, 128>>>(pool, desc, fc1W, fc1b, n1g, n1b, fc2W, fc2b, out, X, C);
}

// round 16
// speedup vs baseline: 1.4033x; 1.0420x over previous
#include <cuda_runtime.h>
#include <cuda_fp16.h>
#include <cstdint>

#define DF 128
#define NMAX 100000
#define EMAX 1600000
#define GMAX 1024
#define XS_STRIDE 144

// persistent scratch (no allocations allowed)
__device__ __half g_h16a[(size_t)NMAX * DF];
__device__ __half g_h16b[(size_t)NMAX * DF];
__device__ float  g_pool[(size_t)GMAX * DF];
__device__ int    g_deg[NMAX];
__device__ int    g_rowptr[NMAX + 1];
__device__ int    g_cursor[NMAX];
__device__ int    g_csrc[EMAX];
__device__ int    g_bsum[1024];

#define BAR_SYNC(id, cnt)   asm volatile("bar.sync %0, %1;"   :: "r"(id), "r"(cnt) : "memory")
#define BAR_ARRIVE(id, cnt) asm volatile("bar.arrive %0, %1;" :: "r"(id), "r"(cnt) : "memory")

// ---------------------------------------------------------------------------
// CSR build: degree histogram -> exclusive scan -> scatter
__global__ void deg_kernel(const int* __restrict__ dst, int* __restrict__ deg, int E) {
    int i = blockIdx.x * blockDim.x + threadIdx.x;
    if (i < E) atomicAdd(&deg[__ldg(dst + i)], 1);
}

__global__ void scan1_kernel(const int* __restrict__ deg, int* __restrict__ rowptr,
                             int* __restrict__ bsum, int N) {
    __shared__ int sh[1024];
    int tid = threadIdx.x;
    int i = blockIdx.x * 1024 + tid;
    int v = (i < N) ? deg[i] : 0;
    sh[tid] = v;
    __syncthreads();
    #pragma unroll
    for (int off = 1; off < 1024; off <<= 1) {
        int t = (tid >= off) ? sh[tid - off] : 0;
        __syncthreads();
        sh[tid] += t;
        __syncthreads();
    }
    if (i < N) rowptr[i] = sh[tid] - v;
    if (tid == 1023) bsum[blockIdx.x] = sh[1023];
}

__global__ void scan2_kernel(int* __restrict__ bsum, int nb) {
    if (threadIdx.x == 0 && blockIdx.x == 0) {
        int acc = 0;
        for (int i = 0; i < nb; ++i) {
            int v = bsum[i];
            bsum[i] = acc;
            acc += v;
        }
    }
}

__global__ void scan3_kernel(int* __restrict__ rowptr, const int* __restrict__ bsum,
                             int* __restrict__ cursor, int N, int E) {
    int i = blockIdx.x * 1024 + threadIdx.x;
    if (i < N) {
        int v = rowptr[i] + bsum[blockIdx.x];
        rowptr[i] = v;
        cursor[i] = v;
    }
    if (i == 0) rowptr[N] = E;
}

__global__ void scatter_kernel(const int* __restrict__ src, const int* __restrict__ dst,
                               int* __restrict__ cursor, int* __restrict__ csrc, int E) {
    int i = blockIdx.x * blockDim.x + threadIdx.x;
    if (i < E) {
        int pos = atomicAdd(&cursor[__ldg(dst + i)], 1);
        csrc[pos] = __ldg(src + i);
    }
}

// ---------------------------------------------------------------------------
__global__ void cvt16_kernel(const float* __restrict__ src, __half* __restrict__ dst, int n4) {
    int i = blockIdx.x * blockDim.x + threadIdx.x;
    if (i < n4) {
        float4 v = *(const float4*)(src + i * 4);
        __half2 p2[2];
        p2[0] = __floats2half2_rn(v.x, v.y);
        p2[1] = __floats2half2_rn(v.z, v.w);
        *(float2*)(dst + i * 4) = *(float2*)p2;
    }
}

// ---------------------------------------------------------------------------
__device__ __forceinline__ void acc8(float* acc, uint4 p) {
    float2 f0 = __half22float2(*(__half2*)&p.x);
    float2 f1 = __half22float2(*(__half2*)&p.y);
    float2 f2 = __half22float2(*(__half2*)&p.z);
    float2 f3 = __half22float2(*(__half2*)&p.w);
    acc[0] += f0.x; acc[1] += f0.y;
    acc[2] += f1.x; acc[3] += f1.y;
    acc[4] += f2.x; acc[5] += f2.y;
    acc[6] += f3.x; acc[7] += f3.y;
}

// ---------------------------------------------------------------------------
// Warp-specialized fused GIN layer: 1024 threads, triple-buffered Xs.
// Warps 0-15 (producers): gather (neighbor unroll x8, MLP=8) + residual.
// Warps 16-31 (consumers): HMMA m16n8k16 MLP + LN/ReLU x2 -> fp16 out.
// Named barriers: full[buf]=1+buf (1..3), empty[buf]=4+buf (4..6), count 1024
// (512 arrive + 512 sync); consumer-internal barrier 7 (count 512).
__global__ void __launch_bounds__(1024, 1)
layer_fused(const __half* __restrict__ hin16,
            const int* __restrict__ rowptr, const int* __restrict__ csrc,
            const float* __restrict__ epsArr, int layer,
            const float* __restrict__ W1, const float* __restrict__ b1,
            const float* __restrict__ g1, const float* __restrict__ be1,
            const float* __restrict__ W2, const float* __restrict__ b2,
            const float* __restrict__ ng, const float* __restrict__ nb,
            __half* __restrict__ out16,
            int nrows, int ntiles) {
    extern __shared__ __align__(16) char smraw[];
    __half* Ws1 = (__half*)smraw;                        // 16384 halfs
    __half* Ws2 = Ws1 + 128 * 128;                       // 16384 halfs
    __half* XsB = Ws2 + 128 * 128;                       // 3 x 128*144 halfs
    float*  prm = (float*)(XsB + 3 * 128 * XS_STRIDE);   // 6*128 floats
    float* bs1 = prm, *gs1 = prm + 128, *es1 = prm + 256;
    float* bs2 = prm + 384, *gs2 = prm + 512, *es2 = prm + 640;

    int tid  = threadIdx.x;
    int lane = tid & 31, warp = tid >> 5;

    // Stage W1/W2 as half, interleaved: Ws[(s*128+n)*16 + pos(k&15)]
    for (int idx = tid; idx < 4096; idx += 1024) {
        int k  = idx >> 5;
        int n4 = idx & 31;
        int s  = k >> 4, kq = k & 15;
        int pos = (kq & 1) | (((kq >> 3) & 1) << 1) | (((kq >> 1) & 3) << 2);
        size_t go = (size_t)k * DF + n4 * 4;
        float4 wa = *(const float4*)(W1 + go);
        float4 wb = *(const float4*)(W2 + go);
        int base = ((s * 128) + n4 * 4) * 16 + pos;
        Ws1[base]      = __float2half(wa.x);
        Ws1[base + 16] = __float2half(wa.y);
        Ws1[base + 32] = __float2half(wa.z);
        Ws1[base + 48] = __float2half(wa.w);
        Ws2[base]      = __float2half(wb.x);
        Ws2[base + 16] = __float2half(wb.y);
        Ws2[base + 32] = __float2half(wb.z);
        Ws2[base + 48] = __float2half(wb.w);
    }
    if (tid < DF) {
        bs1[tid] = b1[tid]; gs1[tid] = g1[tid]; es1[tid] = be1[tid];
        bs2[tid] = b2[tid]; gs2[tid] = ng[tid]; es2[tid] = nb[tid];
    }
    __syncthreads();

    float escale = 1.0f + epsArr[layer];

    if (warp < 16) {
        // ======================= PRODUCER =======================
        int pw = warp;
        int hw = lane >> 4;
        int hl = lane & 15;
        int lt = 0;
        for (int tile = blockIdx.x; tile < ntiles; tile += gridDim.x, ++lt) {
            int buf = lt % 3;
            if (lt >= 3) BAR_SYNC(4 + buf, 1024);      // wait empty[buf]
            __half* Xs = XsB + buf * (128 * XS_STRIDE);
            int rowBlk = tile * 128;
            for (int rr = 0; rr < 4; ++rr) {
                int r   = pw * 8 + hw * 4 + rr;
                int row = rowBlk + r;
                float acc[8] = {0.f, 0.f, 0.f, 0.f, 0.f, 0.f, 0.f, 0.f};
                if (row < nrows) {
                    int beg = __ldg(rowptr + row), end = __ldg(rowptr + row + 1);
                    int i = beg;
                    // neighbor unroll x8 (scalar index loads; 8 gathers in flight)
                    for (; i + 8 <= end; i += 8) {
                        int u0 = __ldg(csrc + i),     u1 = __ldg(csrc + i + 1);
                        int u2 = __ldg(csrc + i + 2), u3 = __ldg(csrc + i + 3);
                        int u4 = __ldg(csrc + i + 4), u5 = __ldg(csrc + i + 5);
                        int u6 = __ldg(csrc + i + 6), u7 = __ldg(csrc + i + 7);
                        uint4 p0 = *(const uint4*)(hin16 + (size_t)u0 * DF + hl * 8);
                        uint4 p1 = *(const uint4*)(hin16 + (size_t)u1 * DF + hl * 8);
                        uint4 p2 = *(const uint4*)(hin16 + (size_t)u2 * DF + hl * 8);
                        uint4 p3 = *(const uint4*)(hin16 + (size_t)u3 * DF + hl * 8);
                        uint4 p4 = *(const uint4*)(hin16 + (size_t)u4 * DF + hl * 8);
                        uint4 p5 = *(const uint4*)(hin16 + (size_t)u5 * DF + hl * 8);
                        uint4 p6 = *(const uint4*)(hin16 + (size_t)u6 * DF + hl * 8);
                        uint4 p7 = *(const uint4*)(hin16 + (size_t)u7 * DF + hl * 8);
                        acc8(acc, p0); acc8(acc, p1); acc8(acc, p2); acc8(acc, p3);
                        acc8(acc, p4); acc8(acc, p5); acc8(acc, p6); acc8(acc, p7);
                    }
                    for (; i + 4 <= end; i += 4) {
                        int u0 = __ldg(csrc + i),     u1 = __ldg(csrc + i + 1);
                        int u2 = __ldg(csrc + i + 2), u3 = __ldg(csrc + i + 3);
                        uint4 p0 = *(const uint4*)(hin16 + (size_t)u0 * DF + hl * 8);
                        uint4 p1 = *(const uint4*)(hin16 + (size_t)u1 * DF + hl * 8);
                        uint4 p2 = *(const uint4*)(hin16 + (size_t)u2 * DF + hl * 8);
                        uint4 p3 = *(const uint4*)(hin16 + (size_t)u3 * DF + hl * 8);
                        acc8(acc, p0); acc8(acc, p1); acc8(acc, p2); acc8(acc, p3);
                    }
                    for (; i < end; ++i) {
                        int u = __ldg(csrc + i);
                        uint4 p = *(const uint4*)(hin16 + (size_t)u * DF + hl * 8);
                        acc8(acc, p);
                    }
                    uint4 hp = *(const uint4*)(hin16 + (size_t)row * DF + hl * 8);
                    float2 h0 = __half22float2(*(__half2*)&hp.x);
                    float2 h1 = __half22float2(*(__half2*)&hp.y);
                    float2 h2 = __half22float2(*(__half2*)&hp.z);
                    float2 h3 = __half22float2(*(__half2*)&hp.w);
                    acc[0] = fmaf(escale, h0.x, acc[0]);
                    acc[1] = fmaf(escale, h0.y, acc[1]);
                    acc[2] = fmaf(escale, h1.x, acc[2]);
                    acc[3] = fmaf(escale, h1.y, acc[3]);
                    acc[4] = fmaf(escale, h2.x, acc[4]);
                    acc[5] = fmaf(escale, h2.y, acc[5]);
                    acc[6] = fmaf(escale, h3.x, acc[6]);
                    acc[7] = fmaf(escale, h3.y, acc[7]);
                }
                #pragma unroll
                for (int cc = 0; cc < 2; ++cc) {
                    int c4 = 2 * hl + cc;
                    int a = (c4 & 1) * 8 + (c4 & 2);
                    __half* p = Xs + r * XS_STRIDE + (c4 >> 2) * 16 + a;
                    float* A = acc + cc * 4;
                    *(__half2*)p       = __floats2half2_rn(A[0], A[1]);
                    *(__half2*)(p + 4) = __floats2half2_rn(A[2], A[3]);
                }
            }
            BAR_ARRIVE(1 + buf, 1024);                 // signal full[buf]
        }
    } else {
        // ======================= CONSUMER =======================
        int cw = warp - 16;
        int wr = (cw & 7) * 16;
        int wc = (cw >> 3) * 64;
        int fr = lane >> 2;
        int qd = lane & 3;
        int lt = 0;
        for (int tile = blockIdx.x; tile < ntiles; tile += gridDim.x, ++lt) {
            int buf = lt % 3;
            BAR_SYNC(1 + buf, 1024);                   // wait full[buf]
            __half* Xs = XsB + buf * (128 * XS_STRIDE);
            int rowBlk = tile * 128;

            float acc[8][4];

            // ---- pass 1: X @ W1 ----
            #pragma unroll
            for (int j = 0; j < 8; ++j) {
                acc[j][0] = 0.f; acc[j][1] = 0.f; acc[j][2] = 0.f; acc[j][3] = 0.f;
            }
            #pragma unroll
            for (int s = 0; s < 8; ++s) {
                uint2 av0 = *(const uint2*)(Xs + (wr + fr)     * XS_STRIDE + s * 16 + qd * 4);
                uint2 av1 = *(const uint2*)(Xs + (wr + fr + 8) * XS_STRIDE + s * 16 + qd * 4);
                #pragma unroll
                for (int j = 0; j < 8; ++j) {
                    uint2 bv = *(const uint2*)(Ws1 + ((s * 128) + wc + j * 8 + fr) * 16 + qd * 4);
                    asm volatile(
                        "mma.sync.aligned.m16n8k16.row.col.f32.f16.f16.f32 "
                        "{%0,%1,%2,%3}, {%4,%5,%6,%7}, {%8,%9}, {%0,%1,%2,%3};"
                        : "+f"(acc[j][0]), "+f"(acc[j][1]), "+f"(acc[j][2]), "+f"(acc[j][3])
                        : "r"(av0.x), "r"(av1.x), "r"(av0.y), "r"(av1.y),
                          "r"(bv.x), "r"(bv.y));
                }
            }
            BAR_SYNC(7, 512);
            #pragma unroll
            for (int j = 0; j < 8; ++j) {
                int n = wc + j * 8 + qd * 2;
                *(__half2*)(Xs + (wr + fr)     * XS_STRIDE + n) = __floats2half2_rn(acc[j][0], acc[j][1]);
                *(__half2*)(Xs + (wr + fr + 8) * XS_STRIDE + n) = __floats2half2_rn(acc[j][2], acc[j][3]);
            }
            BAR_SYNC(7, 512);

            // ---- LN1 + ReLU (in-place re-permute) ----
            {
                float4 b4 = ((const float4*)bs1)[lane];
                float4 g4 = ((const float4*)gs1)[lane];
                float4 e4 = ((const float4*)es1)[lane];
                #pragma unroll
                for (int rr = 0; rr < 8; ++rr) {
                    int lrow = cw * 8 + rr;
                    __half* R = Xs + lrow * XS_STRIDE;
                    const __half2* qq2 = (const __half2*)(R + lane * 4);
                    float2 f0 = __half22float2(qq2[0]);
                    float2 f1 = __half22float2(qq2[1]);
                    float a0 = f0.x + b4.x, a1 = f0.y + b4.y, a2 = f1.x + b4.z, a3 = f1.y + b4.w;
                    float s = a0 + a1 + a2 + a3;
                    float q = a0 * a0 + a1 * a1 + a2 * a2 + a3 * a3;
                    #pragma unroll
                    for (int off = 16; off > 0; off >>= 1) {
                        s += __shfl_xor_sync(0xFFFFFFFFu, s, off);
                        q += __shfl_xor_sync(0xFFFFFFFFu, q, off);
                    }
                    float mu   = s * (1.0f / 128.0f);
                    float var  = q * (1.0f / 128.0f) - mu * mu;
                    float rstd = rsqrtf(var + 1e-5f);
                    float o0 = fmaxf(0.f, (a0 - mu) * rstd * g4.x + e4.x);
                    float o1 = fmaxf(0.f, (a1 - mu) * rstd * g4.y + e4.y);
                    float o2 = fmaxf(0.f, (a2 - mu) * rstd * g4.z + e4.z);
                    float o3 = fmaxf(0.f, (a3 - mu) * rstd * g4.w + e4.w);
                    int a = (lane & 1) * 8 + (lane & 2);
                    __half* p = R + (lane >> 2) * 16 + a;
                    *(__half2*)p       = __floats2half2_rn(o0, o1);
                    *(__half2*)(p + 4) = __floats2half2_rn(o2, o3);
                }
            }
            BAR_SYNC(7, 512);

            // ---- pass 2: Y @ W2 ----
            #pragma unroll
            for (int j = 0; j < 8; ++j) {
                acc[j][0] = 0.f; acc[j][1] = 0.f; acc[j][2] = 0.f; acc[j][3] = 0.f;
            }
            #pragma unroll
            for (int s = 0; s < 8; ++s) {
                uint2 av0 = *(const uint2*)(Xs + (wr + fr)     * XS_STRIDE + s * 16 + qd * 4);
                uint2 av1 = *(const uint2*)(Xs + (wr + fr + 8) * XS_STRIDE + s * 16 + qd * 4);
                #pragma unroll
                for (int j = 0; j < 8; ++j) {
                    uint2 bv = *(const uint2*)(Ws2 + ((s * 128) + wc + j * 8 + fr) * 16 + qd * 4);
                    asm volatile(
                        "mma.sync.aligned.m16n8k16.row.col.f32.f16.f16.f32 "
                        "{%0,%1,%2,%3}, {%4,%5,%6,%7}, {%8,%9}, {%0,%1,%2,%3};"
                        : "+f"(acc[j][0]), "+f"(acc[j][1]), "+f"(acc[j][2]), "+f"(acc[j][3])
                        : "r"(av0.x), "r"(av1.x), "r"(av0.y), "r"(av1.y),
                          "r"(bv.x), "r"(bv.y));
                }
            }
            BAR_SYNC(7, 512);
            #pragma unroll
            for (int j = 0; j < 8; ++j) {
                int n = wc + j * 8 + qd * 2;
                *(__half2*)(Xs + (wr + fr)     * XS_STRIDE + n) = __floats2half2_rn(acc[j][0], acc[j][1]);
                *(__half2*)(Xs + (wr + fr + 8) * XS_STRIDE + n) = __floats2half2_rn(acc[j][2], acc[j][3]);
            }
            BAR_SYNC(7, 512);

            // ---- LN2 + ReLU -> fp16 gmem ----
            {
                float4 b4 = ((const float4*)bs2)[lane];
                float4 g4 = ((const float4*)gs2)[lane];
                float4 e4 = ((const float4*)es2)[lane];
                #pragma unroll
                for (int rr = 0; rr < 8; ++rr) {
                    int lrow = cw * 8 + rr;
                    int grow = rowBlk + lrow;
                    const __half2* qq2 = (const __half2*)(Xs + lrow * XS_STRIDE + lane * 4);
                    float2 f0 = __half22float2(qq2[0]);
                    float2 f1 = __half22float2(qq2[1]);
                    float a0 = f0.x + b4.x, a1 = f0.y + b4.y, a2 = f1.x + b4.z, a3 = f1.y + b4.w;
                    float s = a0 + a1 + a2 + a3;
                    float q = a0 * a0 + a1 * a1 + a2 * a2 + a3 * a3;
                    #pragma unroll
                    for (int off = 16; off > 0; off >>= 1) {
                        s += __shfl_xor_sync(0xFFFFFFFFu, s, off);
                        q += __shfl_xor_sync(0xFFFFFFFFu, q, off);
                    }
                    float mu   = s * (1.0f / 128.0f);
                    float var  = q * (1.0f / 128.0f) - mu * mu;
                    float rstd = rsqrtf(var + 1e-5f);
                    float o0 = fmaxf(0.f, (a0 - mu) * rstd * g4.x + e4.x);
                    float o1 = fmaxf(0.f, (a1 - mu) * rstd * g4.y + e4.y);
                    float o2 = fmaxf(0.f, (a2 - mu) * rstd * g4.z + e4.z);
                    float o3 = fmaxf(0.f, (a3 - mu) * rstd * g4.w + e4.w);
                    if (grow < nrows) {
                        __half2 p2[2];
                        p2[0] = __floats2half2_rn(o0, o1);
                        p2[1] = __floats2half2_rn(o2, o3);
                        *(float2*)(out16 + (size_t)grow * DF + lane * 4) = *(float2*)p2;
                    }
                }
            }
            BAR_ARRIVE(4 + buf, 1024);                 // signal empty[buf]
        }
    }
}

// ---------------------------------------------------------------------------
__global__ void pool_kernel(const __half* __restrict__ h16, const int* __restrict__ gid,
                            float* __restrict__ pool, int N) {
    int c  = threadIdx.x;
    int n0 = blockIdx.x * 128;
    if (n0 >= N) return;
    int curg = __ldg(gid + n0);
    float acc = 0.f;
    #pragma unroll 4
    for (int i = 0; i < 128; ++i) {
        int n = n0 + i;
        if (n >= N) break;
        int g = __ldg(gid + n);
        if (g != curg) {
            atomicAdd(&pool[(size_t)curg * DF + c], acc);
            acc = 0.f;
            curg = g;
        }
        acc += __half2float(h16[(size_t)n * DF + c]);
    }
    atomicAdd(&pool[(size_t)curg * DF + c], acc);
}

// ---------------------------------------------------------------------------
__global__ void head_kernel(const float* __restrict__ pool, const float* __restrict__ desc,
                            const float* __restrict__ fc1W, const float* __restrict__ fc1b,
                            const float* __restrict__ n1g, const float* __restrict__ n1b,
                            const float* __restrict__ fc2W, const float* __restrict__ fc2b,
                            float* __restrict__ out, int X, int C) {
    int g = blockIdx.x;
    int t = threadIdx.x;
    int warp = t >> 5, lane = t & 31;

    __shared__ float xin[DF + 64];
    __shared__ float ss[4], qq[4];

    xin[t] = pool[(size_t)g * DF + t];
    if (t < X) xin[DF + t] = desc[(size_t)g * X + t];
    __syncthreads();

    int K = DF + X;
    float acc = fc1b[t];
    for (int k = 0; k < K; ++k)
        acc = fmaf(xin[k], __ldg(fc1W + (size_t)k * DF + t), acc);

    float s = acc, q = acc * acc;
    #pragma unroll
    for (int off = 16; off > 0; off >>= 1) {
        s += __shfl_xor_sync(0xFFFFFFFFu, s, off);
        q += __shfl_xor_sync(0xFFFFFFFFu, q, off);
    }
    if (lane == 0) { ss[warp] = s; qq[warp] = q; }
    __syncthreads();
    s = ss[0] + ss[1] + ss[2] + ss[3];
    q = qq[0] + qq[1] + qq[2] + qq[3];
    float mu   = s * (1.0f / 128.0f);
    float var  = q * (1.0f / 128.0f) - mu * mu;
    float rstd = rsqrtf(var + 1e-5f);
    float y = fmaxf(0.f, (acc - mu) * rstd * n1g[t] + n1b[t]);

    for (int c = 0; c < C; ++c) {
        float p = y * __ldg(fc2W + (size_t)t * C + c);
        #pragma unroll
        for (int off = 16; off > 0; off >>= 1)
            p += __shfl_xor_sync(0xFFFFFFFFu, p, off);
        __syncthreads();
        if (lane == 0) ss[warp] = p;
        __syncthreads();
        if (t == 0) out[(size_t)g * C + c] = ss[0] + ss[1] + ss[2] + ss[3] + fc2b[c];
    }
}

// ---------------------------------------------------------------------------
extern "C" void kernel_launch(void* const* d_in, const int* in_sizes, int n_in,
                              void* d_out, int out_size) {
    const float* h    = (const float*)d_in[0];
    const float* desc = (const float*)d_in[1];
    const int*   src  = (const int*)d_in[2];
    const int*   dst  = (const int*)d_in[3];
    const int*   gid  = (const int*)d_in[4];
    const float* W1   = (const float*)d_in[5];
    const float* b1   = (const float*)d_in[6];
    const float* g1   = (const float*)d_in[7];
    const float* be1  = (const float*)d_in[8];
    const float* W2   = (const float*)d_in[9];
    const float* b2   = (const float*)d_in[10];
    const float* eps  = (const float*)d_in[11];
    const float* ng   = (const float*)d_in[12];
    const float* nb   = (const float*)d_in[13];
    const float* fc1W = (const float*)d_in[14];
    const float* fc1b = (const float*)d_in[15];
    const float* n1g  = (const float*)d_in[16];
    const float* n1b  = (const float*)d_in[17];
    const float* fc2W = (const float*)d_in[18];
    const float* fc2b = (const float*)d_in[19];
    float* out = (float*)d_out;

    int N = in_sizes[0] / DF;
    int E = in_sizes[2];
    int L = in_sizes[11];
    int X = in_sizes[14] / DF - DF;
    if (X <= 0) X = 16;
    int G = in_sizes[1] / X;
    int C = in_sizes[18] / DF;
    if (C <= 0) C = 1;
    if (N > NMAX) N = NMAX;
    if (G > GMAX) G = GMAX;
    if (E > EMAX) E = EMAX;

    float *pool;
    __half *h16a, *h16b;
    int *degp, *rowptr, *cursor, *csrc, *bsum;
    cudaGetSymbolAddress((void**)&h16a, g_h16a);
    cudaGetSymbolAddress((void**)&h16b, g_h16b);
    cudaGetSymbolAddress((void**)&pool, g_pool);
    cudaGetSymbolAddress((void**)&degp, g_deg);
    cudaGetSymbolAddress((void**)&rowptr, g_rowptr);
    cudaGetSymbolAddress((void**)&cursor, g_cursor);
    cudaGetSymbolAddress((void**)&csrc, g_csrc);
    cudaGetSymbolAddress((void**)&bsum, g_bsum);

    const int SMEM_BYTES = (2 * 128 * 128 + 3 * 128 * XS_STRIDE) * 2 + 6 * DF * 4; // 179,200
    cudaFuncSetAttribute(layer_fused,
                         cudaFuncAttributeMaxDynamicSharedMemorySize, SMEM_BYTES);

    // --- CSR build + fp16 convert of input h (once per launch) ---
    int nb_scan = (N + 1023) / 1024;
    cudaMemsetAsync(degp, 0, (size_t)N * sizeof(int));
    deg_kernel<<<(E + 255) / 256, 256>>>(dst, degp, E);
    scan1_kernel<<<nb_scan, 1024>>>(degp, rowptr, bsum, N);
    scan2_kernel<<<1, 32>>>(bsum, nb_scan);
    scan3_kernel<<<nb_scan, 1024>>>(rowptr, bsum, cursor, N, E);
    scatter_kernel<<<(E + 255) / 256, 256>>>(src, dst, cursor, csrc, E);
    int nd4 = N * (DF / 4);
    cvt16_kernel<<<(nd4 + 255) / 256, 256>>>(h, h16a, nd4);

    int ntiles = (N + 127) / 128;
    int fgrid = ntiles < 148 ? ntiles : 148;

    __half* hin  = h16a;
    __half* hout = h16b;
    for (int l = 0; l < L; ++l) {
        layer_fused<<<fgrid, 1024, SMEM_BYTES>>>(
            hin, rowptr, csrc, eps, l,
            W1 + (size_t)l * DF * DF, b1 + (size_t)l * DF,
            g1 + (size_t)l * DF, be1 + (size_t)l * DF,
            W2 + (size_t)l * DF * DF, b2 + (size_t)l * DF,
            ng + (size_t)l * DF, nb + (size_t)l * DF,
            hout, N, ntiles);
        __half* t = hin; hin = hout; hout = t;
    }

    cudaMemsetAsync(pool, 0, (size_t)G * DF * sizeof(float));
    pool_kernel<<<(N + 127) / 128, 128>>>(hin, gid, pool, N);
    head_kernel<<<G, 128>>>(pool, desc, fc1W, fc1b, n1g, n1b, fc2W, fc2b, out, X, C);
}